// round 1
// baseline (speedup 1.0000x reference)
#include <cuda_runtime.h>

#define NN   50000
#define FIN  128
#define HID  256
#define NCLS 40
#define EE   600000
#define BN_EPS 1e-5f

// ---------------- device scratch (no allocations allowed) ----------------
__device__ float g_aggx[NN * FIN];            // x + sum_{src->i} x_src
__device__ int   g_deg[NN];                   // in-degree per node
__device__ float g_h1[(size_t)NN * HID];      // relu(BN1(agg1 @ W1 + b1))
__device__ float g_y[NN * NCLS];              // h1 @ W2 (no bias)
__device__ int   g_idx64;                     // 1 if edge_index is int64

// ---------------- edge-index dtype detection (device-side) ---------------
__global__ void detect_kernel(const unsigned int* __restrict__ ei) {
    // If int64, every value < 50000 so all high words (odd 32-bit words) are 0.
    int t = threadIdx.x;
    unsigned any = 0;
    for (int i = t; i < 1024; i += 32) any |= ei[2 * i + 1];
#pragma unroll
    for (int off = 16; off > 0; off >>= 1) any |= __shfl_xor_sync(0xFFFFFFFFu, any, off);
    if (t == 0) g_idx64 = (any == 0) ? 1 : 0;
}

__device__ __forceinline__ void load_edge(const void* ei, int e, int& s, int& d) {
    if (g_idx64) {
        const long long* p = (const long long*)ei;
        s = (int)p[e];
        d = (int)p[EE + e];
    } else {
        const int* p = (const int*)ei;
        s = p[e];
        d = p[EE + e];
    }
}

// ---------------- init: aggx = x, deg = 0 ----------------
__global__ void init_kernel(const float* __restrict__ x) {
    int t = blockIdx.x * blockDim.x + threadIdx.x;   // over NN*32 float4 slots
    if (t >= NN * 32) return;
    ((float4*)g_aggx)[t] = __ldg((const float4*)x + t);
    if ((t & 31) == 0) g_deg[t >> 5] = 0;
}

// ---------------- scatter layer 1: aggx[dst] += x[src], deg[dst]++ -------
__global__ void scatter1_kernel(const float* __restrict__ x, const void* __restrict__ ei) {
    int t = blockIdx.x * blockDim.x + threadIdx.x;   // over EE*32 (edge, float4)
    if (t >= EE * 32) return;
    int e = t >> 5;
    int q = t & 31;
    int s, d;
    load_edge(ei, e, s, d);
    float4 v = __ldg((const float4*)x + (size_t)s * 32 + q);
    float* p = g_aggx + (size_t)d * FIN + q * 4;
    atomicAdd(p + 0, v.x);
    atomicAdd(p + 1, v.y);
    atomicAdd(p + 2, v.z);
    atomicAdd(p + 3, v.w);
    if (q == 0) atomicAdd(&g_deg[d], 1);
}

// ---------------- GEMM1: h1 = relu(BN1( A @ W1 + b1 )) -------------------
// A(r,k) = aggx[r][k]*s0[k] + (1+deg[r])*t0[k]   (BN0 folded into A-load)
// Tile 128x128, 256 threads, 8x8 micro-tile, BK=16.
__global__ void __launch_bounds__(256, 2) gemm1_kernel(
    const float* __restrict__ W1, const float* __restrict__ b1,
    const float* __restrict__ bn0g, const float* __restrict__ bn0b,
    const float* __restrict__ bn0m, const float* __restrict__ bn0v,
    const float* __restrict__ bn1g, const float* __restrict__ bn1b,
    const float* __restrict__ bn1m, const float* __restrict__ bn1v) {
    __shared__ float As[16][132];
    __shared__ float Bs[16][132];
    __shared__ float s0s[FIN], t0s[FIN];
    __shared__ float s1s[128], t1s[128];
    __shared__ float cntS[128];

    const int tid = threadIdx.x;
    const int mBase = blockIdx.x * 128;
    const int nb = blockIdx.y * 128;

    if (tid < 128) {
        // BN0 affine (global feature index = tid, FIN==128)
        float s0 = bn0g[tid] * rsqrtf(bn0v[tid] + BN_EPS);
        s0s[tid] = s0;
        t0s[tid] = bn0b[tid] - bn0m[tid] * s0;
        // BN1 affine for this block's columns
        int col = nb + tid;
        float s1 = bn1g[col] * rsqrtf(bn1v[col] + BN_EPS);
        s1s[tid] = s1;
        t1s[tid] = bn1b[col] - bn1m[col] * s1;
        // per-row count (1 + deg)
        int row = mBase + tid;
        cntS[tid] = (row < NN) ? (1.0f + (float)g_deg[row]) : 0.0f;
    }
    __syncthreads();

    const int ty = tid >> 4;          // 0..15
    const int tx = tid & 15;          // 0..15

    float acc[8][8];
#pragma unroll
    for (int i = 0; i < 8; i++)
#pragma unroll
        for (int j = 0; j < 8; j++) acc[i][j] = 0.0f;

    for (int kb = 0; kb < FIN; kb += 16) {
        // ---- load A tile (with BN0 fold), store transposed As[k][m] ----
#pragma unroll
        for (int p = 0; p < 2; p++) {
            int rit = p * 64 + (tid >> 2);
            int kq = (tid & 3) * 4;
            int grow = mBase + rit;
            float4 f = make_float4(0.f, 0.f, 0.f, 0.f);
            if (grow < NN) f = *(const float4*)(g_aggx + (size_t)grow * FIN + kb + kq);
            float4 s4 = *(const float4*)(s0s + kb + kq);
            float4 t4 = *(const float4*)(t0s + kb + kq);
            float c = cntS[rit];
            As[kq + 0][rit] = f.x * s4.x + c * t4.x;
            As[kq + 1][rit] = f.y * s4.y + c * t4.y;
            As[kq + 2][rit] = f.z * s4.z + c * t4.z;
            As[kq + 3][rit] = f.w * s4.w + c * t4.w;
        }
        // ---- load B tile (W1 rows kb..kb+15, cols nb..nb+127) ----
#pragma unroll
        for (int p = 0; p < 2; p++) {
            int kr = p * 8 + (tid >> 5);
            int c4 = (tid & 31) * 4;
            float4 w = __ldg((const float4*)(W1 + (size_t)(kb + kr) * HID + nb + c4));
            *(float4*)&Bs[kr][c4] = w;
        }
        __syncthreads();

#pragma unroll
        for (int k = 0; k < 16; k++) {
            float4 a0 = *(const float4*)&As[k][ty * 8];
            float4 a1 = *(const float4*)&As[k][ty * 8 + 4];
            float4 b0 = *(const float4*)&Bs[k][tx * 8];
            float4 b1v = *(const float4*)&Bs[k][tx * 8 + 4];
            float a[8] = {a0.x, a0.y, a0.z, a0.w, a1.x, a1.y, a1.z, a1.w};
            float b[8] = {b0.x, b0.y, b0.z, b0.w, b1v.x, b1v.y, b1v.z, b1v.w};
#pragma unroll
            for (int i = 0; i < 8; i++)
#pragma unroll
                for (int j = 0; j < 8; j++) acc[i][j] = fmaf(a[i], b[j], acc[i][j]);
        }
        __syncthreads();
    }

    // ---- epilogue: +b1, BN1, relu, store h1 ----
#pragma unroll
    for (int i = 0; i < 8; i++) {
        int row = mBase + ty * 8 + i;
        if (row < NN) {
#pragma unroll
            for (int j = 0; j < 8; j++) {
                int lc = tx * 8 + j;
                int col = nb + lc;
                float z = acc[i][j] + __ldg(b1 + col);
                float h = fmaxf(z * s1s[lc] + t1s[lc], 0.0f);
                g_h1[(size_t)row * HID + col] = h;
            }
        }
    }
}

// ---------------- GEMM2: y = h1 @ W2 ; out = y + b2 ----------------------
// Tile 256 rows x 40 cols, 256 threads, each thread 4 rows x 10 cols, BK=16.
__global__ void __launch_bounds__(256, 2) gemm2_kernel(
    const float* __restrict__ W2, const float* __restrict__ b2,
    float* __restrict__ out) {
    __shared__ float As[16][260];
    __shared__ float Ws[16][48];
    __shared__ float b2s[NCLS];

    const int tid = threadIdx.x;
    const int mBase = blockIdx.x * 256;
    if (tid < NCLS) b2s[tid] = b2[tid];

    const int rloc = tid & 63;   // 0..63 -> rows rloc*4..+3
    const int cg = tid >> 6;     // 0..3  -> cols cg*10..+9

    float acc[4][10];
#pragma unroll
    for (int i = 0; i < 4; i++)
#pragma unroll
        for (int j = 0; j < 10; j++) acc[i][j] = 0.0f;

    for (int kb = 0; kb < HID; kb += 16) {
        // ---- A tile: 256 rows x 16 k, transposed ----
#pragma unroll
        for (int p = 0; p < 4; p++) {
            int rit = p * 64 + (tid >> 2);
            int kq = (tid & 3) * 4;
            int grow = mBase + rit;
            float4 f = make_float4(0.f, 0.f, 0.f, 0.f);
            if (grow < NN) f = *(const float4*)(g_h1 + (size_t)grow * HID + kb + kq);
            As[kq + 0][rit] = f.x;
            As[kq + 1][rit] = f.y;
            As[kq + 2][rit] = f.z;
            As[kq + 3][rit] = f.w;
        }
        // ---- W2 chunk packed: Ws[k][cg*12 + j] (j<10 valid, pad 0) ----
        for (int l = tid; l < 16 * 48; l += 256) {
            int k = l / 48;
            int c = l % 48;
            int wcg = c / 12;
            int j = c % 12;
            float v = 0.0f;
            if (j < 10) v = __ldg(W2 + (size_t)(kb + k) * NCLS + wcg * 10 + j);
            Ws[k][c] = v;
        }
        __syncthreads();

#pragma unroll
        for (int k = 0; k < 16; k++) {
            float4 a = *(const float4*)&As[k][rloc * 4];
            float4 wA = *(const float4*)&Ws[k][cg * 12];
            float4 wB = *(const float4*)&Ws[k][cg * 12 + 4];
            float4 wC = *(const float4*)&Ws[k][cg * 12 + 8];
            float av[4] = {a.x, a.y, a.z, a.w};
            float wv[10] = {wA.x, wA.y, wA.z, wA.w, wB.x, wB.y, wB.z, wB.w, wC.x, wC.y};
#pragma unroll
            for (int i = 0; i < 4; i++)
#pragma unroll
                for (int j = 0; j < 10; j++) acc[i][j] = fmaf(av[i], wv[j], acc[i][j]);
        }
        __syncthreads();
    }

#pragma unroll
    for (int i = 0; i < 4; i++) {
        int row = mBase + rloc * 4 + i;
        if (row < NN) {
            int base = row * NCLS + cg * 10;
#pragma unroll
            for (int j = 0; j < 10; j++) {
                float y = acc[i][j];
                g_y[base + j] = y;
                out[base + j] = y + b2s[cg * 10 + j];
            }
        }
    }
}

// ---------------- scatter layer 2: out[dst] += y[src] (width 40) ---------
__global__ void scatter2_kernel(const void* __restrict__ ei, float* __restrict__ out) {
    int t = blockIdx.x * blockDim.x + threadIdx.x;   // over EE*10 (edge, float4)
    if (t >= EE * 10) return;
    int e = t / 10;
    int q = t - e * 10;
    int s, d;
    load_edge(ei, e, s, d);
    float4 v = __ldg((const float4*)g_y + (size_t)s * 10 + q);
    float* p = out + (size_t)d * NCLS + q * 4;
    atomicAdd(p + 0, v.x);
    atomicAdd(p + 1, v.y);
    atomicAdd(p + 2, v.z);
    atomicAdd(p + 3, v.w);
}

// --------------------------------------------------------------------------
extern "C" void kernel_launch(void* const* d_in, const int* in_sizes, int n_in,
                              void* d_out, int out_size) {
    const float* x    = (const float*)d_in[0];
    const void*  ei   = d_in[1];
    const float* bn0g = (const float*)d_in[2];
    const float* bn0b = (const float*)d_in[3];
    const float* bn0m = (const float*)d_in[4];
    const float* bn0v = (const float*)d_in[5];
    const float* W1   = (const float*)d_in[6];
    const float* b1   = (const float*)d_in[7];
    const float* bn1g = (const float*)d_in[8];
    const float* bn1b = (const float*)d_in[9];
    const float* bn1m = (const float*)d_in[10];
    const float* bn1v = (const float*)d_in[11];
    const float* W2   = (const float*)d_in[12];
    const float* b2   = (const float*)d_in[13];
    float* out = (float*)d_out;

    detect_kernel<<<1, 32>>>((const unsigned int*)ei);
    init_kernel<<<(NN * 32 + 255) / 256, 256>>>(x);
    scatter1_kernel<<<(EE * 32 + 255) / 256, 256>>>(x, ei);
    dim3 g1((NN + 127) / 128, HID / 128);
    gemm1_kernel<<<g1, 256>>>(W1, b1, bn0g, bn0b, bn0m, bn0v, bn1g, bn1b, bn1m, bn1v);
    gemm2_kernel<<<(NN + 255) / 256, 256>>>(W2, b2, out);
    scatter2_kernel<<<(EE * 10 + 255) / 256, 256>>>(ei, out);
}

// round 2
// speedup vs baseline: 1.4144x; 1.4144x over previous
#include <cuda_runtime.h>

#define NN   50000
#define FIN  128
#define HID  256
#define NCLS 40
#define EE   600000
#define BN_EPS 1e-5f

// ---------------- device scratch (no allocations allowed) ----------------
__device__ float g_aggx[NN * FIN];            // x + sum_{src->i} x_src
__device__ int   g_deg[NN];                   // in-degree per node
__device__ float g_h1[(size_t)NN * HID];      // relu(BN1(agg1 @ W1 + b1))
__device__ float g_y[NN * NCLS];              // h1 @ W2 (no bias)
__device__ int   g_idx64;                     // 1 if edge_index is int64

// ---------------- f32x2 packed-math helpers ------------------------------
__device__ __forceinline__ unsigned long long dup2(float v) {
    unsigned long long r;
    asm("mov.b64 %0, {%1, %1};" : "=l"(r) : "f"(v));
    return r;
}
__device__ __forceinline__ unsigned long long fma2(unsigned long long a,
                                                   unsigned long long b,
                                                   unsigned long long c) {
    unsigned long long d;
    asm("fma.rn.f32x2 %0, %1, %2, %3;" : "=l"(d) : "l"(a), "l"(b), "l"(c));
    return d;
}
__device__ __forceinline__ void unpack2(unsigned long long v, float& lo, float& hi) {
    asm("mov.b64 {%0, %1}, %2;" : "=f"(lo), "=f"(hi) : "l"(v));
}
__device__ __forceinline__ void red_v4(float* p, float4 v) {
    asm volatile("red.global.add.v4.f32 [%0], {%1, %2, %3, %4};"
                 :: "l"(p), "f"(v.x), "f"(v.y), "f"(v.z), "f"(v.w) : "memory");
}

// ---------------- edge-index dtype detection (device-side) ---------------
__global__ void detect_kernel(const unsigned int* __restrict__ ei) {
    int t = threadIdx.x;
    unsigned any = 0;
    for (int i = t; i < 1024; i += 32) any |= ei[2 * i + 1];
#pragma unroll
    for (int off = 16; off > 0; off >>= 1) any |= __shfl_xor_sync(0xFFFFFFFFu, any, off);
    if (t == 0) g_idx64 = (any == 0) ? 1 : 0;
}

__device__ __forceinline__ void load_edge(const void* ei, int e, int& s, int& d) {
    if (g_idx64) {
        const long long* p = (const long long*)ei;
        s = (int)p[e];
        d = (int)p[EE + e];
    } else {
        const int* p = (const int*)ei;
        s = p[e];
        d = p[EE + e];
    }
}

// ---------------- init: aggx = x, deg = 0 ----------------
__global__ void init_kernel(const float* __restrict__ x) {
    int t = blockIdx.x * blockDim.x + threadIdx.x;   // over NN*32 float4 slots
    if (t >= NN * 32) return;
    ((float4*)g_aggx)[t] = __ldg((const float4*)x + t);
    if ((t & 31) == 0) g_deg[t >> 5] = 0;
}

// ---------------- scatter layer 1: aggx[dst] += x[src], deg[dst]++ -------
__global__ void scatter1_kernel(const float* __restrict__ x, const void* __restrict__ ei) {
    int t = blockIdx.x * blockDim.x + threadIdx.x;   // over EE*32 (edge, float4)
    if (t >= EE * 32) return;
    int e = t >> 5;
    int q = t & 31;
    int s, d;
    load_edge(ei, e, s, d);
    float4 v = __ldg((const float4*)x + (size_t)s * 32 + q);
    red_v4(g_aggx + (size_t)d * FIN + q * 4, v);
    if (q == 0) atomicAdd(&g_deg[d], 1);
}

// ---------------- GEMM1: h1 = relu(BN1( A @ W1 + b1 )) -------------------
// A(r,k) = aggx[r][k]*s0[k] + (1+deg[r])*t0[k]   (BN0 folded into A-load)
// Tile 128x128, 256 threads, 8x8 micro-tile via f32x2 packed FMA, BK=16.
__global__ void __launch_bounds__(256, 2) gemm1_kernel(
    const float* __restrict__ W1, const float* __restrict__ b1,
    const float* __restrict__ bn0g, const float* __restrict__ bn0b,
    const float* __restrict__ bn0m, const float* __restrict__ bn0v,
    const float* __restrict__ bn1g, const float* __restrict__ bn1b,
    const float* __restrict__ bn1m, const float* __restrict__ bn1v) {
    __shared__ __align__(16) float As[16][132];
    __shared__ __align__(16) float Bs[16][132];
    __shared__ float s0s[FIN], t0s[FIN];
    __shared__ float s1s[128], t1s[128];
    __shared__ float cntS[128];

    const int tid = threadIdx.x;
    const int mBase = blockIdx.x * 128;
    const int nb = blockIdx.y * 128;

    if (tid < 128) {
        float s0 = bn0g[tid] * rsqrtf(bn0v[tid] + BN_EPS);
        s0s[tid] = s0;
        t0s[tid] = bn0b[tid] - bn0m[tid] * s0;
        int col = nb + tid;
        float s1 = bn1g[col] * rsqrtf(bn1v[col] + BN_EPS);
        s1s[tid] = s1;
        t1s[tid] = bn1b[col] - bn1m[col] * s1;
        int row = mBase + tid;
        cntS[tid] = (row < NN) ? (1.0f + (float)g_deg[row]) : 0.0f;
    }
    __syncthreads();

    const int ty = tid >> 4;          // 0..15 -> rows ty*8..+7
    const int tx = tid & 15;          // 0..15 -> cols tx*8..+7

    // acc2[i][j] holds rows (ty*8+2i, ty*8+2i+1), col tx*8+j as f32x2
    unsigned long long acc2[4][8];
#pragma unroll
    for (int i = 0; i < 4; i++)
#pragma unroll
        for (int j = 0; j < 8; j++) acc2[i][j] = 0ULL;

    for (int kb = 0; kb < FIN; kb += 16) {
        // ---- load A tile (BN0 folded), stored transposed As[k][m] ----
#pragma unroll
        for (int p = 0; p < 2; p++) {
            int rit = p * 64 + (tid >> 2);
            int kq = (tid & 3) * 4;
            int grow = mBase + rit;
            float4 f = make_float4(0.f, 0.f, 0.f, 0.f);
            if (grow < NN) f = *(const float4*)(g_aggx + (size_t)grow * FIN + kb + kq);
            float4 s4 = *(const float4*)(s0s + kb + kq);
            float4 t4 = *(const float4*)(t0s + kb + kq);
            float c = cntS[rit];
            As[kq + 0][rit] = f.x * s4.x + c * t4.x;
            As[kq + 1][rit] = f.y * s4.y + c * t4.y;
            As[kq + 2][rit] = f.z * s4.z + c * t4.z;
            As[kq + 3][rit] = f.w * s4.w + c * t4.w;
        }
        // ---- load B tile (W1 rows kb..kb+15, cols nb..nb+127) ----
#pragma unroll
        for (int p = 0; p < 2; p++) {
            int kr = p * 8 + (tid >> 5);
            int c4 = (tid & 31) * 4;
            float4 w = __ldg((const float4*)(W1 + (size_t)(kb + kr) * HID + nb + c4));
            *(float4*)&Bs[kr][c4] = w;
        }
        __syncthreads();

#pragma unroll
        for (int k = 0; k < 16; k++) {
            // row pairs straight from shared as 64-bit loads (no packing)
            const unsigned long long* ap = (const unsigned long long*)&As[k][ty * 8];
            unsigned long long a2[4] = {ap[0], ap[1], ap[2], ap[3]};
            float4 b0 = *(const float4*)&Bs[k][tx * 8];
            float4 b1v = *(const float4*)&Bs[k][tx * 8 + 4];
            unsigned long long bd[8] = {dup2(b0.x), dup2(b0.y), dup2(b0.z), dup2(b0.w),
                                        dup2(b1v.x), dup2(b1v.y), dup2(b1v.z), dup2(b1v.w)};
#pragma unroll
            for (int i = 0; i < 4; i++)
#pragma unroll
                for (int j = 0; j < 8; j++) acc2[i][j] = fma2(a2[i], bd[j], acc2[i][j]);
        }
        __syncthreads();
    }

    // ---- epilogue: +b1, BN1, relu, store h1 ----
#pragma unroll
    for (int i = 0; i < 4; i++) {
        int row0 = mBase + ty * 8 + 2 * i;
#pragma unroll
        for (int j = 0; j < 8; j++) {
            int lc = tx * 8 + j;
            int col = nb + lc;
            float lo, hi;
            unpack2(acc2[i][j], lo, hi);
            float bb = __ldg(b1 + col);
            float s1 = s1s[lc], t1 = t1s[lc];
            if (row0 < NN)
                g_h1[(size_t)row0 * HID + col] = fmaxf((lo + bb) * s1 + t1, 0.0f);
            if (row0 + 1 < NN)
                g_h1[(size_t)(row0 + 1) * HID + col] = fmaxf((hi + bb) * s1 + t1, 0.0f);
        }
    }
}

// ---------------- GEMM2: y = h1 @ W2 ; out = y + b2 ----------------------
// Tile 256 rows x 40 cols, 256 threads, 4x10 micro-tile via f32x2, BK=16.
__global__ void __launch_bounds__(256, 2) gemm2_kernel(
    const float* __restrict__ W2, const float* __restrict__ b2,
    float* __restrict__ out) {
    __shared__ __align__(16) float As[16][260];
    __shared__ float Ws[16][48];
    __shared__ float b2s[NCLS];

    const int tid = threadIdx.x;
    const int mBase = blockIdx.x * 256;
    if (tid < NCLS) b2s[tid] = b2[tid];

    const int rloc = tid & 63;   // rows rloc*4..+3
    const int cg = tid >> 6;     // cols cg*10..+9

    // acc2[i][j]: rows (rloc*4+2i, rloc*4+2i+1), col cg*10+j
    unsigned long long acc2[2][10];
#pragma unroll
    for (int i = 0; i < 2; i++)
#pragma unroll
        for (int j = 0; j < 10; j++) acc2[i][j] = 0ULL;

    for (int kb = 0; kb < HID; kb += 16) {
#pragma unroll
        for (int p = 0; p < 4; p++) {
            int rit = p * 64 + (tid >> 2);
            int kq = (tid & 3) * 4;
            int grow = mBase + rit;
            float4 f = make_float4(0.f, 0.f, 0.f, 0.f);
            if (grow < NN) f = *(const float4*)(g_h1 + (size_t)grow * HID + kb + kq);
            As[kq + 0][rit] = f.x;
            As[kq + 1][rit] = f.y;
            As[kq + 2][rit] = f.z;
            As[kq + 3][rit] = f.w;
        }
        for (int l = tid; l < 16 * 48; l += 256) {
            int k = l / 48;
            int c = l % 48;
            int wcg = c / 12;
            int j = c % 12;
            float v = 0.0f;
            if (j < 10) v = __ldg(W2 + (size_t)(kb + k) * NCLS + wcg * 10 + j);
            Ws[k][c] = v;
        }
        __syncthreads();

#pragma unroll
        for (int k = 0; k < 16; k++) {
            const unsigned long long* ap = (const unsigned long long*)&As[k][rloc * 4];
            unsigned long long a2[2] = {ap[0], ap[1]};
            float4 wA = *(const float4*)&Ws[k][cg * 12];
            float4 wB = *(const float4*)&Ws[k][cg * 12 + 4];
            float4 wC = *(const float4*)&Ws[k][cg * 12 + 8];
            float wv[10] = {wA.x, wA.y, wA.z, wA.w, wB.x, wB.y, wB.z, wB.w, wC.x, wC.y};
#pragma unroll
            for (int i = 0; i < 2; i++)
#pragma unroll
                for (int j = 0; j < 10; j++) acc2[i][j] = fma2(a2[i], dup2(wv[j]), acc2[i][j]);
        }
        __syncthreads();
    }

#pragma unroll
    for (int i = 0; i < 2; i++) {
        int row0 = mBase + rloc * 4 + 2 * i;
#pragma unroll
        for (int j = 0; j < 10; j++) {
            float lo, hi;
            unpack2(acc2[i][j], lo, hi);
            int c = cg * 10 + j;
            if (row0 < NN) {
                g_y[row0 * NCLS + c] = lo;
                out[row0 * NCLS + c] = lo + b2s[c];
            }
            if (row0 + 1 < NN) {
                g_y[(row0 + 1) * NCLS + c] = hi;
                out[(row0 + 1) * NCLS + c] = hi + b2s[c];
            }
        }
    }
}

// ---------------- scatter layer 2: out[dst] += y[src] (width 40) ---------
__global__ void scatter2_kernel(const void* __restrict__ ei, float* __restrict__ out) {
    int t = blockIdx.x * blockDim.x + threadIdx.x;   // over EE*10 (edge, float4)
    if (t >= EE * 10) return;
    int e = t / 10;
    int q = t - e * 10;
    int s, d;
    load_edge(ei, e, s, d);
    float4 v = __ldg((const float4*)g_y + (size_t)s * 10 + q);
    red_v4(out + (size_t)d * NCLS + q * 4, v);
}

// --------------------------------------------------------------------------
extern "C" void kernel_launch(void* const* d_in, const int* in_sizes, int n_in,
                              void* d_out, int out_size) {
    const float* x    = (const float*)d_in[0];
    const void*  ei   = d_in[1];
    const float* bn0g = (const float*)d_in[2];
    const float* bn0b = (const float*)d_in[3];
    const float* bn0m = (const float*)d_in[4];
    const float* bn0v = (const float*)d_in[5];
    const float* W1   = (const float*)d_in[6];
    const float* b1   = (const float*)d_in[7];
    const float* bn1g = (const float*)d_in[8];
    const float* bn1b = (const float*)d_in[9];
    const float* bn1m = (const float*)d_in[10];
    const float* bn1v = (const float*)d_in[11];
    const float* W2   = (const float*)d_in[12];
    const float* b2   = (const float*)d_in[13];
    float* out = (float*)d_out;

    detect_kernel<<<1, 32>>>((const unsigned int*)ei);
    init_kernel<<<(NN * 32 + 255) / 256, 256>>>(x);
    scatter1_kernel<<<(EE * 32 + 255) / 256, 256>>>(x, ei);
    dim3 g1((NN + 127) / 128, HID / 128);
    gemm1_kernel<<<g1, 256>>>(W1, b1, bn0g, bn0b, bn0m, bn0v, bn1g, bn1b, bn1m, bn1v);
    gemm2_kernel<<<(NN + 255) / 256, 256>>>(W2, b2, out);
    scatter2_kernel<<<(EE * 10 + 255) / 256, 256>>>(ei, out);
}

// round 3
// speedup vs baseline: 1.7043x; 1.2049x over previous
#include <cuda_runtime.h>

#define NN   50000
#define FIN  128
#define HID  256
#define NCLS 40
#define EE   600000
#define BN_EPS 1e-5f
#define NBLK ((NN + 1023) / 1024)   // 49 scan blocks

// ---------------- device scratch (no allocations allowed) ----------------
__device__ float g_aggx[NN * FIN];            // x + sum_{src->i} x_src
__device__ int   g_deg[NN];                   // in-degree per node
__device__ int   g_rowptr[NN + 1];            // CSR row pointers (by dst)
__device__ int   g_cursor[NN];                // fill cursors
__device__ int   g_csr[EE];                   // src indices grouped by dst
__device__ int   g_bsum[NBLK];                // scan partial sums
__device__ int   g_boff[NBLK];                // scan block offsets
__device__ float g_h1[(size_t)NN * HID];      // relu(BN1(agg1 @ W1 + b1))
__device__ float g_y[NN * NCLS];              // h1 @ W2 (no bias)
__device__ int   g_idx64;                     // 1 if edge_index is int64

// ---------------- f32x2 packed-math helpers ------------------------------
__device__ __forceinline__ unsigned long long dup2(float v) {
    unsigned long long r;
    asm("mov.b64 %0, {%1, %1};" : "=l"(r) : "f"(v));
    return r;
}
__device__ __forceinline__ unsigned long long fma2(unsigned long long a,
                                                   unsigned long long b,
                                                   unsigned long long c) {
    unsigned long long d;
    asm("fma.rn.f32x2 %0, %1, %2, %3;" : "=l"(d) : "l"(a), "l"(b), "l"(c));
    return d;
}
__device__ __forceinline__ void unpack2(unsigned long long v, float& lo, float& hi) {
    asm("mov.b64 {%0, %1}, %2;" : "=f"(lo), "=f"(hi) : "l"(v));
}

// ---------------- edge-index dtype detection (device-side) ---------------
__global__ void detect_kernel(const unsigned int* __restrict__ ei) {
    int t = threadIdx.x;
    unsigned any = 0;
    for (int i = t; i < 1024; i += 32) any |= ei[2 * i + 1];
#pragma unroll
    for (int off = 16; off > 0; off >>= 1) any |= __shfl_xor_sync(0xFFFFFFFFu, any, off);
    if (t == 0) g_idx64 = (any == 0) ? 1 : 0;
}

__device__ __forceinline__ void load_edge(const void* ei, int e, int& s, int& d) {
    if (g_idx64) {
        const long long* p = (const long long*)ei;
        s = (int)p[e];
        d = (int)p[EE + e];
    } else {
        const int* p = (const int*)ei;
        s = p[e];
        d = p[EE + e];
    }
}

// ---------------- CSR build --------------------------------------------
__global__ void zero_deg_kernel() {
    int i = blockIdx.x * blockDim.x + threadIdx.x;
    if (i < NN) g_deg[i] = 0;
}

__global__ void count_kernel(const void* __restrict__ ei) {
    int e = blockIdx.x * blockDim.x + threadIdx.x;
    if (e >= EE) return;
    int s, d;
    load_edge(ei, e, s, d);
    atomicAdd(&g_deg[d], 1);
}

// block partial sums of deg
__global__ void scan1_kernel() {
    __shared__ int sh[1024];
    int t = threadIdx.x;
    int i = blockIdx.x * 1024 + t;
    sh[t] = (i < NN) ? g_deg[i] : 0;
    __syncthreads();
#pragma unroll
    for (int off = 512; off > 0; off >>= 1) {
        if (t < off) sh[t] += sh[t + off];
        __syncthreads();
    }
    if (t == 0) g_bsum[blockIdx.x] = sh[0];
}

// serial exclusive scan over NBLK partials
__global__ void scan2_kernel() {
    if (threadIdx.x == 0) {
        int acc = 0;
        for (int b = 0; b < NBLK; b++) {
            g_boff[b] = acc;
            acc += g_bsum[b];
        }
        g_rowptr[NN] = acc;
    }
}

// in-block exclusive scan + block offset -> rowptr, cursor
__global__ void scan3_kernel() {
    __shared__ int sh[1024];
    int t = threadIdx.x;
    int i = blockIdx.x * 1024 + t;
    int v = (i < NN) ? g_deg[i] : 0;
    sh[t] = v;
    __syncthreads();
#pragma unroll
    for (int off = 1; off < 1024; off <<= 1) {
        int add = (t >= off) ? sh[t - off] : 0;
        __syncthreads();
        sh[t] += add;
        __syncthreads();
    }
    if (i < NN) {
        int excl = sh[t] - v + g_boff[blockIdx.x];
        g_rowptr[i] = excl;
        g_cursor[i] = excl;
    }
}

__global__ void fill_kernel(const void* __restrict__ ei) {
    int e = blockIdx.x * blockDim.x + threadIdx.x;
    if (e >= EE) return;
    int s, d;
    load_edge(ei, e, s, d);
    int pos = atomicAdd(&g_cursor[d], 1);
    g_csr[pos] = s;
}

// ---------------- gather layer 1: aggx[i] = x[i] + sum_{j in N(i)} x[j] --
__global__ void gather1_kernel(const float* __restrict__ x) {
    int w = (blockIdx.x * blockDim.x + threadIdx.x) >> 5;   // node
    int q = threadIdx.x & 31;                               // float4 column
    if (w >= NN) return;
    const float4* xb = (const float4*)x;
    float4 acc = __ldg(xb + (size_t)w * 32 + q);
    int beg = g_rowptr[w];
    int end = g_rowptr[w + 1];
#pragma unroll 2
    for (int e = beg; e < end; e++) {
        int j = g_csr[e];
        float4 v = __ldg(xb + (size_t)j * 32 + q);
        acc.x += v.x; acc.y += v.y; acc.z += v.z; acc.w += v.w;
    }
    ((float4*)g_aggx)[(size_t)w * 32 + q] = acc;
}

// ---------------- GEMM1: h1 = relu(BN1( A @ W1 + b1 )) -------------------
// A(r,k) = aggx[r][k]*s0[k] + (1+deg[r])*t0[k]   (BN0 folded into A-load)
__global__ void __launch_bounds__(256, 2) gemm1_kernel(
    const float* __restrict__ W1, const float* __restrict__ b1,
    const float* __restrict__ bn0g, const float* __restrict__ bn0b,
    const float* __restrict__ bn0m, const float* __restrict__ bn0v,
    const float* __restrict__ bn1g, const float* __restrict__ bn1b,
    const float* __restrict__ bn1m, const float* __restrict__ bn1v) {
    __shared__ __align__(16) float As[16][132];
    __shared__ __align__(16) float Bs[16][132];
    __shared__ float s0s[FIN], t0s[FIN];
    __shared__ float s1s[128], t1s[128];
    __shared__ float cntS[128];

    const int tid = threadIdx.x;
    const int mBase = blockIdx.x * 128;
    const int nb = blockIdx.y * 128;

    if (tid < 128) {
        float s0 = bn0g[tid] * rsqrtf(bn0v[tid] + BN_EPS);
        s0s[tid] = s0;
        t0s[tid] = bn0b[tid] - bn0m[tid] * s0;
        int col = nb + tid;
        float s1 = bn1g[col] * rsqrtf(bn1v[col] + BN_EPS);
        s1s[tid] = s1;
        t1s[tid] = bn1b[col] - bn1m[col] * s1;
        int row = mBase + tid;
        cntS[tid] = (row < NN) ? (1.0f + (float)g_deg[row]) : 0.0f;
    }
    __syncthreads();

    const int ty = tid >> 4;
    const int tx = tid & 15;

    unsigned long long acc2[4][8];
#pragma unroll
    for (int i = 0; i < 4; i++)
#pragma unroll
        for (int j = 0; j < 8; j++) acc2[i][j] = 0ULL;

    for (int kb = 0; kb < FIN; kb += 16) {
#pragma unroll
        for (int p = 0; p < 2; p++) {
            int rit = p * 64 + (tid >> 2);
            int kq = (tid & 3) * 4;
            int grow = mBase + rit;
            float4 f = make_float4(0.f, 0.f, 0.f, 0.f);
            if (grow < NN) f = *(const float4*)(g_aggx + (size_t)grow * FIN + kb + kq);
            float4 s4 = *(const float4*)(s0s + kb + kq);
            float4 t4 = *(const float4*)(t0s + kb + kq);
            float c = cntS[rit];
            As[kq + 0][rit] = f.x * s4.x + c * t4.x;
            As[kq + 1][rit] = f.y * s4.y + c * t4.y;
            As[kq + 2][rit] = f.z * s4.z + c * t4.z;
            As[kq + 3][rit] = f.w * s4.w + c * t4.w;
        }
#pragma unroll
        for (int p = 0; p < 2; p++) {
            int kr = p * 8 + (tid >> 5);
            int c4 = (tid & 31) * 4;
            float4 w = __ldg((const float4*)(W1 + (size_t)(kb + kr) * HID + nb + c4));
            *(float4*)&Bs[kr][c4] = w;
        }
        __syncthreads();

#pragma unroll
        for (int k = 0; k < 16; k++) {
            const unsigned long long* ap = (const unsigned long long*)&As[k][ty * 8];
            unsigned long long a2[4] = {ap[0], ap[1], ap[2], ap[3]};
            float4 b0 = *(const float4*)&Bs[k][tx * 8];
            float4 b1v = *(const float4*)&Bs[k][tx * 8 + 4];
            unsigned long long bd[8] = {dup2(b0.x), dup2(b0.y), dup2(b0.z), dup2(b0.w),
                                        dup2(b1v.x), dup2(b1v.y), dup2(b1v.z), dup2(b1v.w)};
#pragma unroll
            for (int i = 0; i < 4; i++)
#pragma unroll
                for (int j = 0; j < 8; j++) acc2[i][j] = fma2(a2[i], bd[j], acc2[i][j]);
        }
        __syncthreads();
    }

#pragma unroll
    for (int i = 0; i < 4; i++) {
        int row0 = mBase + ty * 8 + 2 * i;
#pragma unroll
        for (int j = 0; j < 8; j++) {
            int lc = tx * 8 + j;
            int col = nb + lc;
            float lo, hi;
            unpack2(acc2[i][j], lo, hi);
            float bb = __ldg(b1 + col);
            float s1 = s1s[lc], t1 = t1s[lc];
            if (row0 < NN)
                g_h1[(size_t)row0 * HID + col] = fmaxf((lo + bb) * s1 + t1, 0.0f);
            if (row0 + 1 < NN)
                g_h1[(size_t)(row0 + 1) * HID + col] = fmaxf((hi + bb) * s1 + t1, 0.0f);
        }
    }
}

// ---------------- GEMM2: g_y = h1 @ W2 (bias applied in gather2) ---------
__global__ void __launch_bounds__(256, 2) gemm2_kernel(const float* __restrict__ W2) {
    __shared__ __align__(16) float As[16][260];
    __shared__ float Ws[16][48];

    const int tid = threadIdx.x;
    const int mBase = blockIdx.x * 256;

    const int rloc = tid & 63;
    const int cg = tid >> 6;

    unsigned long long acc2[2][10];
#pragma unroll
    for (int i = 0; i < 2; i++)
#pragma unroll
        for (int j = 0; j < 10; j++) acc2[i][j] = 0ULL;

    for (int kb = 0; kb < HID; kb += 16) {
#pragma unroll
        for (int p = 0; p < 4; p++) {
            int rit = p * 64 + (tid >> 2);
            int kq = (tid & 3) * 4;
            int grow = mBase + rit;
            float4 f = make_float4(0.f, 0.f, 0.f, 0.f);
            if (grow < NN) f = *(const float4*)(g_h1 + (size_t)grow * HID + kb + kq);
            As[kq + 0][rit] = f.x;
            As[kq + 1][rit] = f.y;
            As[kq + 2][rit] = f.z;
            As[kq + 3][rit] = f.w;
        }
        for (int l = tid; l < 16 * 48; l += 256) {
            int k = l / 48;
            int c = l % 48;
            int wcg = c / 12;
            int j = c % 12;
            float v = 0.0f;
            if (j < 10) v = __ldg(W2 + (size_t)(kb + k) * NCLS + wcg * 10 + j);
            Ws[k][c] = v;
        }
        __syncthreads();

#pragma unroll
        for (int k = 0; k < 16; k++) {
            const unsigned long long* ap = (const unsigned long long*)&As[k][rloc * 4];
            unsigned long long a2[2] = {ap[0], ap[1]};
            float4 wA = *(const float4*)&Ws[k][cg * 12];
            float4 wB = *(const float4*)&Ws[k][cg * 12 + 4];
            float4 wC = *(const float4*)&Ws[k][cg * 12 + 8];
            float wv[10] = {wA.x, wA.y, wA.z, wA.w, wB.x, wB.y, wB.z, wB.w, wC.x, wC.y};
#pragma unroll
            for (int i = 0; i < 2; i++)
#pragma unroll
                for (int j = 0; j < 10; j++) acc2[i][j] = fma2(a2[i], dup2(wv[j]), acc2[i][j]);
        }
        __syncthreads();
    }

#pragma unroll
    for (int i = 0; i < 2; i++) {
        int row0 = mBase + rloc * 4 + 2 * i;
#pragma unroll
        for (int j = 0; j < 10; j++) {
            float lo, hi;
            unpack2(acc2[i][j], lo, hi);
            int c = cg * 10 + j;
            if (row0 < NN) g_y[row0 * NCLS + c] = lo;
            if (row0 + 1 < NN) g_y[(row0 + 1) * NCLS + c] = hi;
        }
    }
}

// ---------------- gather layer 2: out[i] = b2 + y[i] + sum y[j] ----------
// Half-warp (16 threads) per node; lanes 0..9 carry the 10 float4 chunks.
__global__ void gather2_kernel(const float* __restrict__ b2, float* __restrict__ out) {
    int h = (blockIdx.x * blockDim.x + threadIdx.x) >> 4;   // node
    int q = threadIdx.x & 15;                               // float4 chunk
    if (h >= NN || q >= 10) return;
    const float4* yb = (const float4*)g_y;
    float4 acc = __ldg((const float4*)b2 + q);
    float4 v = yb[(size_t)h * 10 + q];
    acc.x += v.x; acc.y += v.y; acc.z += v.z; acc.w += v.w;
    int beg = g_rowptr[h];
    int end = g_rowptr[h + 1];
#pragma unroll 2
    for (int e = beg; e < end; e++) {
        int j = g_csr[e];
        float4 u = __ldg(yb + (size_t)j * 10 + q);
        acc.x += u.x; acc.y += u.y; acc.z += u.z; acc.w += u.w;
    }
    ((float4*)out)[(size_t)h * 10 + q] = acc;
}

// --------------------------------------------------------------------------
extern "C" void kernel_launch(void* const* d_in, const int* in_sizes, int n_in,
                              void* d_out, int out_size) {
    const float* x    = (const float*)d_in[0];
    const void*  ei   = d_in[1];
    const float* bn0g = (const float*)d_in[2];
    const float* bn0b = (const float*)d_in[3];
    const float* bn0m = (const float*)d_in[4];
    const float* bn0v = (const float*)d_in[5];
    const float* W1   = (const float*)d_in[6];
    const float* b1   = (const float*)d_in[7];
    const float* bn1g = (const float*)d_in[8];
    const float* bn1b = (const float*)d_in[9];
    const float* bn1m = (const float*)d_in[10];
    const float* bn1v = (const float*)d_in[11];
    const float* W2   = (const float*)d_in[12];
    const float* b2   = (const float*)d_in[13];
    float* out = (float*)d_out;

    detect_kernel<<<1, 32>>>((const unsigned int*)ei);
    zero_deg_kernel<<<(NN + 255) / 256, 256>>>();
    count_kernel<<<(EE + 255) / 256, 256>>>(ei);
    scan1_kernel<<<NBLK, 1024>>>();
    scan2_kernel<<<1, 32>>>();
    scan3_kernel<<<NBLK, 1024>>>();
    fill_kernel<<<(EE + 255) / 256, 256>>>(ei);
    gather1_kernel<<<(NN * 32 + 255) / 256, 256>>>(x);
    dim3 g1((NN + 127) / 128, HID / 128);
    gemm1_kernel<<<g1, 256>>>(W1, b1, bn0g, bn0b, bn0m, bn0v, bn1g, bn1b, bn1m, bn1v);
    gemm2_kernel<<<(NN + 255) / 256, 256>>>(W2);
    gather2_kernel<<<(NN * 16 + 255) / 256, 256>>>(b2, out);
}

// round 5
// speedup vs baseline: 2.0846x; 1.2231x over previous
#include <cuda_runtime.h>
#include <cuda_bf16.h>

#define NN   50000
#define NNP  50048              // padded to multiple of 128
#define FIN  128
#define HID  256
#define NCLS 40
#define EE   600000
#define BN_EPS 1e-5f
#define NBLK ((NN + 1023) / 1024)

// ---------------- device scratch (zero-initialized, no allocs) -----------
__device__ __nv_bfloat16 g_ahi[(size_t)NNP * FIN];   // hi(BN0-folded agg1)
__device__ __nv_bfloat16 g_alo[(size_t)NNP * FIN];   // lo residual
__device__ __nv_bfloat16 g_w1t_hi[HID * FIN];        // W1^T hi  [n][k]
__device__ __nv_bfloat16 g_w1t_lo[HID * FIN];        // W1^T lo
__device__ float g_s0[FIN], g_t0[FIN];               // BN0 affine
__device__ float g_s1[HID], g_d1[HID];               // BN1 scale, b1*s1+t1
__device__ int   g_deg[NN];
__device__ int   g_rowptr[NN + 1];
__device__ int   g_cursor[NN];
__device__ int   g_csr[EE];
__device__ int   g_bsum[NBLK];
__device__ int   g_boff[NBLK];
__device__ float g_h1[(size_t)NNP * HID];
__device__ float g_y[NN * NCLS];
__device__ int   g_idx64;

// ---------------- f32x2 helpers (gemm2) ----------------------------------
__device__ __forceinline__ unsigned long long dup2(float v) {
    unsigned long long r;
    asm("mov.b64 %0, {%1, %1};" : "=l"(r) : "f"(v));
    return r;
}
__device__ __forceinline__ unsigned long long fma2(unsigned long long a,
                                                   unsigned long long b,
                                                   unsigned long long c) {
    unsigned long long d;
    asm("fma.rn.f32x2 %0, %1, %2, %3;" : "=l"(d) : "l"(a), "l"(b), "l"(c));
    return d;
}
__device__ __forceinline__ void unpack2(unsigned long long v, float& lo, float& hi) {
    asm("mov.b64 {%0, %1}, %2;" : "=f"(lo), "=f"(hi) : "l"(v));
}

// ---------------- mma.sync / ldmatrix helpers (base ISA, sm_80+) ----------
__device__ __forceinline__ unsigned smem_u32(const void* p) {
    unsigned a;
    asm("{ .reg .u64 t; cvta.to.shared.u64 t, %1; cvt.u32.u64 %0, t; }" : "=r"(a) : "l"(p));
    return a;
}
__device__ __forceinline__ void ldsm4(unsigned* r, unsigned addr) {
    asm volatile("ldmatrix.sync.aligned.m8n8.x4.shared.b16 {%0,%1,%2,%3}, [%4];"
                 : "=r"(r[0]), "=r"(r[1]), "=r"(r[2]), "=r"(r[3]) : "r"(addr));
}
__device__ __forceinline__ void mma_bf16(float* d, const unsigned* a, const unsigned* b) {
    asm volatile(
        "mma.sync.aligned.m16n8k16.row.col.f32.bf16.bf16.f32 "
        "{%0,%1,%2,%3}, {%4,%5,%6,%7}, {%8,%9}, {%0,%1,%2,%3};"
        : "+f"(d[0]), "+f"(d[1]), "+f"(d[2]), "+f"(d[3])
        : "r"(a[0]), "r"(a[1]), "r"(a[2]), "r"(a[3]), "r"(b[0]), "r"(b[1]));
}

// ---------------- edge-index dtype detection ------------------------------
__global__ void detect_kernel(const unsigned int* __restrict__ ei) {
    int t = threadIdx.x;
    unsigned any = 0;
    for (int i = t; i < 1024; i += 32) any |= ei[2 * i + 1];
#pragma unroll
    for (int off = 16; off > 0; off >>= 1) any |= __shfl_xor_sync(0xFFFFFFFFu, any, off);
    if (t == 0) g_idx64 = (any == 0) ? 1 : 0;
}

__device__ __forceinline__ void load_edge(const void* ei, int e, int& s, int& d) {
    if (g_idx64) {
        const long long* p = (const long long*)ei;
        s = (int)p[e];
        d = (int)p[EE + e];
    } else {
        const int* p = (const int*)ei;
        s = p[e];
        d = p[EE + e];
    }
}

// ---------------- prep: BN affines + W1^T bf16 split ----------------------
__global__ void prep_kernel(const float* __restrict__ bn0g, const float* __restrict__ bn0b,
                            const float* __restrict__ bn0m, const float* __restrict__ bn0v,
                            const float* __restrict__ W1, const float* __restrict__ b1,
                            const float* __restrict__ bn1g, const float* __restrict__ bn1b,
                            const float* __restrict__ bn1m, const float* __restrict__ bn1v) {
    int t = blockIdx.x * blockDim.x + threadIdx.x;
    if (t < FIN) {
        float s0 = bn0g[t] * rsqrtf(bn0v[t] + BN_EPS);
        g_s0[t] = s0;
        g_t0[t] = bn0b[t] - bn0m[t] * s0;
    }
    if (t < HID) {
        float s1 = bn1g[t] * rsqrtf(bn1v[t] + BN_EPS);
        g_s1[t] = s1;
        g_d1[t] = b1[t] * s1 + (bn1b[t] - bn1m[t] * s1);
    }
    if (t < FIN * HID) {
        int k = t / HID;
        int n = t % HID;
        float w = W1[t];
        __nv_bfloat16 hi = __float2bfloat16_rn(w);
        __nv_bfloat16 lo = __float2bfloat16_rn(w - __bfloat162float(hi));
        g_w1t_hi[n * FIN + k] = hi;
        g_w1t_lo[n * FIN + k] = lo;
    }
}

// ---------------- CSR build ----------------------------------------------
__global__ void zero_deg_kernel() {
    int i = blockIdx.x * blockDim.x + threadIdx.x;
    if (i < NN) g_deg[i] = 0;
}
__global__ void count_kernel(const void* __restrict__ ei) {
    int e = blockIdx.x * blockDim.x + threadIdx.x;
    if (e >= EE) return;
    int s, d;
    load_edge(ei, e, s, d);
    atomicAdd(&g_deg[d], 1);
}
__global__ void scan1_kernel() {
    __shared__ int sh[1024];
    int t = threadIdx.x;
    int i = blockIdx.x * 1024 + t;
    sh[t] = (i < NN) ? g_deg[i] : 0;
    __syncthreads();
#pragma unroll
    for (int off = 512; off > 0; off >>= 1) {
        if (t < off) sh[t] += sh[t + off];
        __syncthreads();
    }
    if (t == 0) g_bsum[blockIdx.x] = sh[0];
}
__global__ void scan2_kernel() {
    if (threadIdx.x == 0) {
        int acc = 0;
        for (int b = 0; b < NBLK; b++) {
            g_boff[b] = acc;
            acc += g_bsum[b];
        }
        g_rowptr[NN] = acc;
    }
}
__global__ void scan3_kernel() {
    __shared__ int sh[1024];
    int t = threadIdx.x;
    int i = blockIdx.x * 1024 + t;
    int v = (i < NN) ? g_deg[i] : 0;
    sh[t] = v;
    __syncthreads();
#pragma unroll
    for (int off = 1; off < 1024; off <<= 1) {
        int add = (t >= off) ? sh[t - off] : 0;
        __syncthreads();
        sh[t] += add;
        __syncthreads();
    }
    if (i < NN) {
        int excl = sh[t] - v + g_boff[blockIdx.x];
        g_rowptr[i] = excl;
        g_cursor[i] = excl;
    }
}
__global__ void fill_kernel(const void* __restrict__ ei) {
    int e = blockIdx.x * blockDim.x + threadIdx.x;
    if (e >= EE) return;
    int s, d;
    load_edge(ei, e, s, d);
    int pos = atomicAdd(&g_cursor[d], 1);
    g_csr[pos] = s;
}

// ---------------- gather1: BN0-folded agg, split to bf16 hi/lo ------------
__global__ void gather1_kernel(const float* __restrict__ x) {
    int w = (blockIdx.x * blockDim.x + threadIdx.x) >> 5;   // node
    int q = threadIdx.x & 31;                               // float4 column
    if (w >= NN) return;
    const float4* xb = (const float4*)x;
    float4 acc = __ldg(xb + (size_t)w * 32 + q);
    int beg = g_rowptr[w];
    int end = g_rowptr[w + 1];
#pragma unroll 2
    for (int e = beg; e < end; e++) {
        int j = g_csr[e];
        float4 v = __ldg(xb + (size_t)j * 32 + q);
        acc.x += v.x; acc.y += v.y; acc.z += v.z; acc.w += v.w;
    }
    float cnt = 1.0f + (float)(end - beg);
    float4 s4 = *(const float4*)(g_s0 + 4 * q);
    float4 t4 = *(const float4*)(g_t0 + 4 * q);
    float a0 = acc.x * s4.x + cnt * t4.x;
    float a1 = acc.y * s4.y + cnt * t4.y;
    float a2 = acc.z * s4.z + cnt * t4.z;
    float a3 = acc.w * s4.w + cnt * t4.w;
    __nv_bfloat16 h0 = __float2bfloat16_rn(a0), h1 = __float2bfloat16_rn(a1);
    __nv_bfloat16 h2 = __float2bfloat16_rn(a2), h3 = __float2bfloat16_rn(a3);
    ushort4 hv, lv;
    hv.x = __bfloat16_as_ushort(h0); hv.y = __bfloat16_as_ushort(h1);
    hv.z = __bfloat16_as_ushort(h2); hv.w = __bfloat16_as_ushort(h3);
    lv.x = __bfloat16_as_ushort(__float2bfloat16_rn(a0 - __bfloat162float(h0)));
    lv.y = __bfloat16_as_ushort(__float2bfloat16_rn(a1 - __bfloat162float(h1)));
    lv.z = __bfloat16_as_ushort(__float2bfloat16_rn(a2 - __bfloat162float(h2)));
    lv.w = __bfloat16_as_ushort(__float2bfloat16_rn(a3 - __bfloat162float(h3)));
    size_t base = (size_t)w * FIN + 4 * q;
    *(ushort4*)(g_ahi + base) = hv;
    *(ushort4*)(g_alo + base) = lv;
}

// ---------------- GEMM1: mma.sync bf16x3, 128x128 tile per CTA ------------
// smem: Ah | Al | Bh | Bl, each 128 rows x 256B (XOR-swizzled 16B chunks)
#define G1_SMEM (4 * 32768)
extern __shared__ char g1_smem[];

__global__ void __launch_bounds__(256, 1) gemm1_kernel() {
    __shared__ float sc1[128], dc1[128];

    const int tid = threadIdx.x;
    const int wid = tid >> 5;
    const int lid = tid & 31;
    const int mBase = blockIdx.x * 128;
    const int nb = blockIdx.y * 128;
    const unsigned sbase = smem_u32(g1_smem);

    if (tid < 128) {
        sc1[tid] = g_s1[nb + tid];
        dc1[tid] = g_d1[nb + tid];
    }

    // ---- load tiles: thread t -> row t/2, chunks (t&1)*8 .. +7 ----
    {
        int row = tid >> 1;
        int half = tid & 1;
        const uint4* ah = (const uint4*)(g_ahi + (size_t)(mBase + row) * FIN);
        const uint4* al = (const uint4*)(g_alo + (size_t)(mBase + row) * FIN);
        const uint4* bh = (const uint4*)(g_w1t_hi + (size_t)(nb + row) * FIN);
        const uint4* bl = (const uint4*)(g_w1t_lo + (size_t)(nb + row) * FIN);
#pragma unroll
        for (int i = 0; i < 8; i++) {
            int c = half * 8 + i;
            unsigned off = row * 256 + ((unsigned)(c ^ (row & 7))) * 16;
            *(uint4*)(g1_smem + off) = ah[c];
            *(uint4*)(g1_smem + 32768 + off) = al[c];
            *(uint4*)(g1_smem + 65536 + off) = bh[c];
            *(uint4*)(g1_smem + 98304 + off) = bl[c];
        }
    }
    __syncthreads();

    const int wm = (wid >> 2) * 64;    // warp M offset (0 or 64)
    const int wn = (wid & 3) * 32;     // warp N offset (0,32,64,96)

    float acc[4][4][4];
#pragma unroll
    for (int mt = 0; mt < 4; mt++)
#pragma unroll
        for (int nt = 0; nt < 4; nt++)
#pragma unroll
            for (int r = 0; r < 4; r++) acc[mt][nt][r] = 0.0f;

    // lane-derived ldmatrix address components
    const int a_r = lid & 15;          // row within m16
    const int a_c = lid >> 4;          // k-chunk select (0/1)
    const int b_r = (lid & 7) + ((lid >> 4) << 3);   // n row within n16 (x4: two n8 mats)
    const int b_c = (lid >> 3) & 1;    // k-chunk select

#pragma unroll
    for (int pass = 0; pass < 3; pass++) {
        unsigned Ab = sbase + ((pass == 2) ? 32768u : 0u);
        unsigned Bb = sbase + 65536u + ((pass == 1) ? 32768u : 0u);
#pragma unroll
        for (int ks = 0; ks < 8; ks++) {
            unsigned a[4][4];
#pragma unroll
            for (int mt = 0; mt < 4; mt++) {
                int row = wm + mt * 16 + a_r;
                int c = ks * 2 + a_c;
                ldsm4(a[mt], Ab + row * 256 + ((unsigned)(c ^ (row & 7))) * 16);
            }
            unsigned b[4][2];
#pragma unroll
            for (int bt = 0; bt < 2; bt++) {
                int row = wn + bt * 16 + b_r;
                int c = ks * 2 + b_c;
                unsigned bb[4];
                ldsm4(bb, Bb + row * 256 + ((unsigned)(c ^ (row & 7))) * 16);
                b[bt * 2 + 0][0] = bb[0]; b[bt * 2 + 0][1] = bb[1];
                b[bt * 2 + 1][0] = bb[2]; b[bt * 2 + 1][1] = bb[3];
            }
#pragma unroll
            for (int mt = 0; mt < 4; mt++)
#pragma unroll
                for (int nt = 0; nt < 4; nt++)
                    mma_bf16(acc[mt][nt], a[mt], b[nt]);
        }
    }

    // ---- epilogue: h1 = max(d*s1 + (b1*s1+t1), 0) ----
    const int rbase = lid >> 2;
    const int cbase = (lid & 3) * 2;
#pragma unroll
    for (int mt = 0; mt < 4; mt++) {
#pragma unroll
        for (int nt = 0; nt < 4; nt++) {
            int n0 = wn + nt * 8 + cbase;
            float s0c = sc1[n0], s1c = sc1[n0 + 1];
            float d0c = dc1[n0], d1c = dc1[n0 + 1];
            int m0 = mBase + wm + mt * 16 + rbase;
            float2 v0, v1;
            v0.x = fmaxf(acc[mt][nt][0] * s0c + d0c, 0.0f);
            v0.y = fmaxf(acc[mt][nt][1] * s1c + d1c, 0.0f);
            v1.x = fmaxf(acc[mt][nt][2] * s0c + d0c, 0.0f);
            v1.y = fmaxf(acc[mt][nt][3] * s1c + d1c, 0.0f);
            *(float2*)(g_h1 + (size_t)m0 * HID + nb + n0) = v0;
            *(float2*)(g_h1 + (size_t)(m0 + 8) * HID + nb + n0) = v1;
        }
    }
}

// ---------------- GEMM2: g_y = h1 @ W2 (bias in gather2) ------------------
__global__ void __launch_bounds__(256, 2) gemm2_kernel(const float* __restrict__ W2) {
    __shared__ __align__(16) float As[16][260];
    __shared__ float Ws[16][48];

    const int tid = threadIdx.x;
    const int mBase = blockIdx.x * 256;
    const int rloc = tid & 63;
    const int cg = tid >> 6;

    unsigned long long acc2[2][10];
#pragma unroll
    for (int i = 0; i < 2; i++)
#pragma unroll
        for (int j = 0; j < 10; j++) acc2[i][j] = 0ULL;

    for (int kb = 0; kb < HID; kb += 16) {
#pragma unroll
        for (int p = 0; p < 4; p++) {
            int rit = p * 64 + (tid >> 2);
            int kq = (tid & 3) * 4;
            int grow = mBase + rit;
            float4 f = make_float4(0.f, 0.f, 0.f, 0.f);
            if (grow < NN) f = *(const float4*)(g_h1 + (size_t)grow * HID + kb + kq);
            As[kq + 0][rit] = f.x;
            As[kq + 1][rit] = f.y;
            As[kq + 2][rit] = f.z;
            As[kq + 3][rit] = f.w;
        }
        for (int l = tid; l < 16 * 48; l += 256) {
            int k = l / 48;
            int c = l % 48;
            int wcg = c / 12;
            int j = c % 12;
            float v = 0.0f;
            if (j < 10) v = __ldg(W2 + (size_t)(kb + k) * NCLS + wcg * 10 + j);
            Ws[k][c] = v;
        }
        __syncthreads();

#pragma unroll
        for (int k = 0; k < 16; k++) {
            const unsigned long long* ap = (const unsigned long long*)&As[k][rloc * 4];
            unsigned long long a2[2] = {ap[0], ap[1]};
            float4 wA = *(const float4*)&Ws[k][cg * 12];
            float4 wB = *(const float4*)&Ws[k][cg * 12 + 4];
            float4 wC = *(const float4*)&Ws[k][cg * 12 + 8];
            float wv[10] = {wA.x, wA.y, wA.z, wA.w, wB.x, wB.y, wB.z, wB.w, wC.x, wC.y};
#pragma unroll
            for (int i = 0; i < 2; i++)
#pragma unroll
                for (int j = 0; j < 10; j++) acc2[i][j] = fma2(a2[i], dup2(wv[j]), acc2[i][j]);
        }
        __syncthreads();
    }

#pragma unroll
    for (int i = 0; i < 2; i++) {
        int row0 = mBase + rloc * 4 + 2 * i;
#pragma unroll
        for (int j = 0; j < 10; j++) {
            float lo, hi;
            unpack2(acc2[i][j], lo, hi);
            int c = cg * 10 + j;
            if (row0 < NN) g_y[row0 * NCLS + c] = lo;
            if (row0 + 1 < NN) g_y[(row0 + 1) * NCLS + c] = hi;
        }
    }
}

// ---------------- gather2: out[i] = b2 + y[i] + sum y[j] ------------------
__global__ void gather2_kernel(const float* __restrict__ b2, float* __restrict__ out) {
    int h = (blockIdx.x * blockDim.x + threadIdx.x) >> 4;
    int q = threadIdx.x & 15;
    if (h >= NN || q >= 10) return;
    const float4* yb = (const float4*)g_y;
    float4 acc = __ldg((const float4*)b2 + q);
    float4 v = yb[(size_t)h * 10 + q];
    acc.x += v.x; acc.y += v.y; acc.z += v.z; acc.w += v.w;
    int beg = g_rowptr[h];
    int end = g_rowptr[h + 1];
#pragma unroll 2
    for (int e = beg; e < end; e++) {
        int j = g_csr[e];
        float4 u = __ldg(yb + (size_t)j * 10 + q);
        acc.x += u.x; acc.y += u.y; acc.z += u.z; acc.w += u.w;
    }
    ((float4*)out)[(size_t)h * 10 + q] = acc;
}

// --------------------------------------------------------------------------
extern "C" void kernel_launch(void* const* d_in, const int* in_sizes, int n_in,
                              void* d_out, int out_size) {
    const float* x    = (const float*)d_in[0];
    const void*  ei   = d_in[1];
    const float* bn0g = (const float*)d_in[2];
    const float* bn0b = (const float*)d_in[3];
    const float* bn0m = (const float*)d_in[4];
    const float* bn0v = (const float*)d_in[5];
    const float* W1   = (const float*)d_in[6];
    const float* b1   = (const float*)d_in[7];
    const float* bn1g = (const float*)d_in[8];
    const float* bn1b = (const float*)d_in[9];
    const float* bn1m = (const float*)d_in[10];
    const float* bn1v = (const float*)d_in[11];
    const float* W2   = (const float*)d_in[12];
    const float* b2   = (const float*)d_in[13];
    float* out = (float*)d_out;

    cudaFuncSetAttribute(gemm1_kernel, cudaFuncAttributeMaxDynamicSharedMemorySize,
                         G1_SMEM);

    detect_kernel<<<1, 32>>>((const unsigned int*)ei);
    prep_kernel<<<(FIN * HID + 255) / 256, 256>>>(bn0g, bn0b, bn0m, bn0v, W1, b1,
                                                  bn1g, bn1b, bn1m, bn1v);
    zero_deg_kernel<<<(NN + 255) / 256, 256>>>();
    count_kernel<<<(EE + 255) / 256, 256>>>(ei);
    scan1_kernel<<<NBLK, 1024>>>();
    scan2_kernel<<<1, 32>>>();
    scan3_kernel<<<NBLK, 1024>>>();
    fill_kernel<<<(EE + 255) / 256, 256>>>(ei);
    gather1_kernel<<<(NN * 32 + 255) / 256, 256>>>(x);
    dim3 g1(NNP / 128, HID / 128);
    gemm1_kernel<<<g1, 256, G1_SMEM>>>();
    gemm2_kernel<<<(NN + 255) / 256, 256>>>(W2);
    gather2_kernel<<<(NN * 16 + 255) / 256, 256>>>(b2, out);
}

// round 6
// speedup vs baseline: 2.3984x; 1.1505x over previous
#include <cuda_runtime.h>
#include <cuda_bf16.h>

#define NN   50000
#define NNP  50176              // padded to multiple of 256
#define FIN  128
#define HID  256
#define NCLS 40
#define EE   600000
#define BN_EPS 1e-5f
#define NBLK ((NN + 1023) / 1024)

// ---------------- device scratch (zero-initialized, no allocs) -----------
__device__ __nv_bfloat16 g_ahi[(size_t)NNP * FIN];   // hi(BN0-folded agg1)
__device__ __nv_bfloat16 g_alo[(size_t)NNP * FIN];   // lo residual
__device__ __nv_bfloat16 g_w1t_hi[HID * FIN];        // W1^T hi  [n][k]
__device__ __nv_bfloat16 g_w1t_lo[HID * FIN];        // W1^T lo
__device__ __nv_bfloat16 g_w2t_hi[48 * HID];         // W2^T hi [n][k], n pad 48
__device__ __nv_bfloat16 g_w2t_lo[48 * HID];         // W2^T lo
__device__ __nv_bfloat16 g_h1hi[(size_t)NNP * HID];  // h1 hi
__device__ __nv_bfloat16 g_h1lo[(size_t)NNP * HID];  // h1 lo
__device__ float g_s0[FIN], g_t0[FIN];               // BN0 affine
__device__ float g_s1[HID], g_d1[HID];               // BN1 scale, b1*s1+t1
__device__ int   g_deg[NN];
__device__ int   g_rowptr[NN + 1];
__device__ int   g_cursor[NN];
__device__ int   g_csr[EE];
__device__ int   g_bsum[NBLK];
__device__ int   g_boff[NBLK];
__device__ float g_y[NN * NCLS];
__device__ int   g_idx64;

// ---------------- mma.sync / ldmatrix helpers (base ISA) ------------------
__device__ __forceinline__ unsigned smem_u32(const void* p) {
    unsigned a;
    asm("{ .reg .u64 t; cvta.to.shared.u64 t, %1; cvt.u32.u64 %0, t; }" : "=r"(a) : "l"(p));
    return a;
}
__device__ __forceinline__ void ldsm4(unsigned* r, unsigned addr) {
    asm volatile("ldmatrix.sync.aligned.m8n8.x4.shared.b16 {%0,%1,%2,%3}, [%4];"
                 : "=r"(r[0]), "=r"(r[1]), "=r"(r[2]), "=r"(r[3]) : "r"(addr));
}
__device__ __forceinline__ void mma_bf16(float* d, const unsigned* a, const unsigned* b) {
    asm volatile(
        "mma.sync.aligned.m16n8k16.row.col.f32.bf16.bf16.f32 "
        "{%0,%1,%2,%3}, {%4,%5,%6,%7}, {%8,%9}, {%0,%1,%2,%3};"
        : "+f"(d[0]), "+f"(d[1]), "+f"(d[2]), "+f"(d[3])
        : "r"(a[0]), "r"(a[1]), "r"(a[2]), "r"(a[3]), "r"(b[0]), "r"(b[1]));
}
__device__ __forceinline__ unsigned packbf2(float a, float b) {
    unsigned r;
    asm("cvt.rn.satfinite.bf16x2.f32 %0, %1, %2;" : "=r"(r) : "f"(b), "f"(a));
    return r;
}

// ---------------- edge-index dtype detection ------------------------------
__global__ void detect_kernel(const unsigned int* __restrict__ ei) {
    int t = threadIdx.x;
    unsigned any = 0;
    for (int i = t; i < 1024; i += 32) any |= ei[2 * i + 1];
#pragma unroll
    for (int off = 16; off > 0; off >>= 1) any |= __shfl_xor_sync(0xFFFFFFFFu, any, off);
    if (t == 0) g_idx64 = (any == 0) ? 1 : 0;
}

__device__ __forceinline__ void load_edge(const void* ei, int e, int& s, int& d) {
    if (g_idx64) {
        const long long* p = (const long long*)ei;
        s = (int)p[e];
        d = (int)p[EE + e];
    } else {
        const int* p = (const int*)ei;
        s = p[e];
        d = p[EE + e];
    }
}

// ---------------- prep: BN affines + W1^T / W2^T bf16 split ---------------
__global__ void prep_kernel(const float* __restrict__ bn0g, const float* __restrict__ bn0b,
                            const float* __restrict__ bn0m, const float* __restrict__ bn0v,
                            const float* __restrict__ W1, const float* __restrict__ b1,
                            const float* __restrict__ bn1g, const float* __restrict__ bn1b,
                            const float* __restrict__ bn1m, const float* __restrict__ bn1v,
                            const float* __restrict__ W2) {
    int t = blockIdx.x * blockDim.x + threadIdx.x;
    if (t < FIN) {
        float s0 = bn0g[t] * rsqrtf(bn0v[t] + BN_EPS);
        g_s0[t] = s0;
        g_t0[t] = bn0b[t] - bn0m[t] * s0;
    }
    if (t < HID) {
        float s1 = bn1g[t] * rsqrtf(bn1v[t] + BN_EPS);
        g_s1[t] = s1;
        g_d1[t] = b1[t] * s1 + (bn1b[t] - bn1m[t] * s1);
    }
    if (t < FIN * HID) {
        int k = t / HID;
        int n = t % HID;
        float w = W1[t];
        __nv_bfloat16 hi = __float2bfloat16_rn(w);
        __nv_bfloat16 lo = __float2bfloat16_rn(w - __bfloat162float(hi));
        g_w1t_hi[n * FIN + k] = hi;
        g_w1t_lo[n * FIN + k] = lo;
    }
    if (t < HID * NCLS) {
        int k = t / NCLS;
        int n = t % NCLS;
        float w = W2[t];
        __nv_bfloat16 hi = __float2bfloat16_rn(w);
        __nv_bfloat16 lo = __float2bfloat16_rn(w - __bfloat162float(hi));
        g_w2t_hi[n * HID + k] = hi;
        g_w2t_lo[n * HID + k] = lo;
    }
}

// ---------------- CSR build ----------------------------------------------
__global__ void zero_deg_kernel() {
    int i = blockIdx.x * blockDim.x + threadIdx.x;
    if (i < NN) g_deg[i] = 0;
}
__global__ void count_kernel(const void* __restrict__ ei) {
    int e = blockIdx.x * blockDim.x + threadIdx.x;
    if (e >= EE) return;
    int d;
    if (g_idx64) d = (int)((const long long*)ei)[EE + e];
    else d = ((const int*)ei)[EE + e];
    atomicAdd(&g_deg[d], 1);
}
__global__ void scan1_kernel() {
    __shared__ int sh[1024];
    int t = threadIdx.x;
    int i = blockIdx.x * 1024 + t;
    sh[t] = (i < NN) ? g_deg[i] : 0;
    __syncthreads();
#pragma unroll
    for (int off = 512; off > 0; off >>= 1) {
        if (t < off) sh[t] += sh[t + off];
        __syncthreads();
    }
    if (t == 0) g_bsum[blockIdx.x] = sh[0];
}
__global__ void scan2_kernel() {
    if (threadIdx.x == 0) {
        int acc = 0;
        for (int b = 0; b < NBLK; b++) {
            g_boff[b] = acc;
            acc += g_bsum[b];
        }
        g_rowptr[NN] = acc;
    }
}
__global__ void scan3_kernel() {
    __shared__ int sh[1024];
    int t = threadIdx.x;
    int i = blockIdx.x * 1024 + t;
    int v = (i < NN) ? g_deg[i] : 0;
    sh[t] = v;
    __syncthreads();
#pragma unroll
    for (int off = 1; off < 1024; off <<= 1) {
        int add = (t >= off) ? sh[t - off] : 0;
        __syncthreads();
        sh[t] += add;
        __syncthreads();
    }
    if (i < NN) {
        int excl = sh[t] - v + g_boff[blockIdx.x];
        g_rowptr[i] = excl;
        g_cursor[i] = excl;
    }
}
__global__ void fill_kernel(const void* __restrict__ ei) {
    int e = blockIdx.x * blockDim.x + threadIdx.x;
    if (e >= EE) return;
    int s, d;
    load_edge(ei, e, s, d);
    int pos = atomicAdd(&g_cursor[d], 1);
    g_csr[pos] = s;
}

// ---------------- gather1: BN0-folded agg, split to bf16 hi/lo ------------
__global__ void gather1_kernel(const float* __restrict__ x) {
    int w = (blockIdx.x * blockDim.x + threadIdx.x) >> 5;   // node
    int q = threadIdx.x & 31;                               // float4 column
    if (w >= NN) return;
    const float4* xb = (const float4*)x;
    float4 acc = __ldg(xb + (size_t)w * 32 + q);
    int beg = g_rowptr[w];
    int end = g_rowptr[w + 1];
#pragma unroll 2
    for (int e = beg; e < end; e++) {
        int j = g_csr[e];
        float4 v = __ldg(xb + (size_t)j * 32 + q);
        acc.x += v.x; acc.y += v.y; acc.z += v.z; acc.w += v.w;
    }
    float cnt = 1.0f + (float)(end - beg);
    float4 s4 = *(const float4*)(g_s0 + 4 * q);
    float4 t4 = *(const float4*)(g_t0 + 4 * q);
    float a0 = acc.x * s4.x + cnt * t4.x;
    float a1 = acc.y * s4.y + cnt * t4.y;
    float a2 = acc.z * s4.z + cnt * t4.z;
    float a3 = acc.w * s4.w + cnt * t4.w;
    __nv_bfloat16 h0 = __float2bfloat16_rn(a0), h1 = __float2bfloat16_rn(a1);
    __nv_bfloat16 h2 = __float2bfloat16_rn(a2), h3 = __float2bfloat16_rn(a3);
    ushort4 hv, lv;
    hv.x = __bfloat16_as_ushort(h0); hv.y = __bfloat16_as_ushort(h1);
    hv.z = __bfloat16_as_ushort(h2); hv.w = __bfloat16_as_ushort(h3);
    lv.x = __bfloat16_as_ushort(__float2bfloat16_rn(a0 - __bfloat162float(h0)));
    lv.y = __bfloat16_as_ushort(__float2bfloat16_rn(a1 - __bfloat162float(h1)));
    lv.z = __bfloat16_as_ushort(__float2bfloat16_rn(a2 - __bfloat162float(h2)));
    lv.w = __bfloat16_as_ushort(__float2bfloat16_rn(a3 - __bfloat162float(h3)));
    size_t base = (size_t)w * FIN + 4 * q;
    *(ushort4*)(g_ahi + base) = hv;
    *(ushort4*)(g_alo + base) = lv;
}

// ---------------- GEMM1: mma.sync bf16x3, 128x128 tile per CTA ------------
// smem: Ah | Al | Bh | Bl, each 128 rows x 256B (XOR-swizzled 16B chunks)
#define G1_SMEM (4 * 32768)
extern __shared__ char dyn_smem[];

__global__ void __launch_bounds__(256, 1) gemm1_kernel() {
    __shared__ float sc1[128], dc1[128];

    const int tid = threadIdx.x;
    const int wid = tid >> 5;
    const int lid = tid & 31;
    const int mBase = blockIdx.x * 128;
    const int nb = blockIdx.y * 128;
    const unsigned sbase = smem_u32(dyn_smem);

    if (tid < 128) {
        sc1[tid] = g_s1[nb + tid];
        dc1[tid] = g_d1[nb + tid];
    }

    // ---- load tiles: thread t -> row t/2, chunks (t&1)*8 .. +7 ----
    {
        int row = tid >> 1;
        int half = tid & 1;
        const uint4* ah = (const uint4*)(g_ahi + (size_t)(mBase + row) * FIN);
        const uint4* al = (const uint4*)(g_alo + (size_t)(mBase + row) * FIN);
        const uint4* bh = (const uint4*)(g_w1t_hi + (size_t)(nb + row) * FIN);
        const uint4* bl = (const uint4*)(g_w1t_lo + (size_t)(nb + row) * FIN);
#pragma unroll
        for (int i = 0; i < 8; i++) {
            int c = half * 8 + i;
            unsigned off = row * 256 + ((unsigned)(c ^ (row & 7))) * 16;
            *(uint4*)(dyn_smem + off) = ah[c];
            *(uint4*)(dyn_smem + 32768 + off) = al[c];
            *(uint4*)(dyn_smem + 65536 + off) = bh[c];
            *(uint4*)(dyn_smem + 98304 + off) = bl[c];
        }
    }
    __syncthreads();

    const int wm = (wid >> 2) * 64;    // warp M offset (0 or 64)
    const int wn = (wid & 3) * 32;     // warp N offset (0,32,64,96)

    float acc[4][4][4];
#pragma unroll
    for (int mt = 0; mt < 4; mt++)
#pragma unroll
        for (int nt = 0; nt < 4; nt++)
#pragma unroll
            for (int r = 0; r < 4; r++) acc[mt][nt][r] = 0.0f;

    const int a_r = lid & 15;
    const int a_c = lid >> 4;
    const int b_r = (lid & 7) + ((lid >> 4) << 3);
    const int b_c = (lid >> 3) & 1;

#pragma unroll
    for (int pass = 0; pass < 3; pass++) {
        unsigned Ab = sbase + ((pass == 2) ? 32768u : 0u);
        unsigned Bb = sbase + 65536u + ((pass == 1) ? 32768u : 0u);
#pragma unroll
        for (int ks = 0; ks < 8; ks++) {
            unsigned a[4][4];
#pragma unroll
            for (int mt = 0; mt < 4; mt++) {
                int row = wm + mt * 16 + a_r;
                int c = ks * 2 + a_c;
                ldsm4(a[mt], Ab + row * 256 + ((unsigned)(c ^ (row & 7))) * 16);
            }
            unsigned b[4][2];
#pragma unroll
            for (int bt = 0; bt < 2; bt++) {
                int row = wn + bt * 16 + b_r;
                int c = ks * 2 + b_c;
                unsigned bb[4];
                ldsm4(bb, Bb + row * 256 + ((unsigned)(c ^ (row & 7))) * 16);
                b[bt * 2 + 0][0] = bb[0]; b[bt * 2 + 0][1] = bb[1];
                b[bt * 2 + 1][0] = bb[2]; b[bt * 2 + 1][1] = bb[3];
            }
#pragma unroll
            for (int mt = 0; mt < 4; mt++)
#pragma unroll
                for (int nt = 0; nt < 4; nt++)
                    mma_bf16(acc[mt][nt], a[mt], b[nt]);
        }
    }

    // ---- epilogue: h = max(d*s1 + (b1*s1+t1), 0), split to bf16 hi/lo ----
    const int rbase = lid >> 2;
    const int cbase = (lid & 3) * 2;
#pragma unroll
    for (int mt = 0; mt < 4; mt++) {
#pragma unroll
        for (int nt = 0; nt < 4; nt++) {
            int n0 = wn + nt * 8 + cbase;
            float s0c = sc1[n0], s1c = sc1[n0 + 1];
            float d0c = dc1[n0], d1c = dc1[n0 + 1];
            int m0 = mBase + wm + mt * 16 + rbase;
#pragma unroll
            for (int half = 0; half < 2; half++) {
                float v0 = fmaxf(acc[mt][nt][half * 2 + 0] * s0c + d0c, 0.0f);
                float v1 = fmaxf(acc[mt][nt][half * 2 + 1] * s1c + d1c, 0.0f);
                unsigned hp = packbf2(v0, v1);
                float h0f = __bfloat162float(__ushort_as_bfloat16((unsigned short)(hp & 0xFFFF)));
                float h1f = __bfloat162float(__ushort_as_bfloat16((unsigned short)(hp >> 16)));
                unsigned lp = packbf2(v0 - h0f, v1 - h1f);
                size_t idx = (size_t)(m0 + half * 8) * HID + nb + n0;
                *(unsigned*)(g_h1hi + idx) = hp;
                *(unsigned*)(g_h1lo + idx) = lp;
            }
        }
    }
}

// ---------------- GEMM2: mma.sync bf16x3, 256x40 tile per CTA -------------
// smem layout (coprime row strides, conflict-free without swizzle):
//   Bh: 48 rows x 528B @ 0      Bl: @ 25344
//   Ah: 256 rows x 80B @ 50688  Al: @ 71168   (k32 chunk)
#define G2_SMEM 91648
#define G2_BH 0
#define G2_BL 25344
#define G2_AH 50688
#define G2_AL 71168

__global__ void __launch_bounds__(256, 2) gemm2_kernel() {
    const int tid = threadIdx.x;
    const int wid = tid >> 5;
    const int lid = tid & 31;
    const int mBase = blockIdx.x * 256;
    const unsigned sb = smem_u32(dyn_smem);

    // ---- load W2^T hi/lo (48 x 256 bf16) ----
    for (int l = tid; l < 48 * 32; l += 256) {
        int row = l >> 5;
        int c = l & 31;
        unsigned off = row * 528 + c * 16;
        *(uint4*)(dyn_smem + G2_BH + off) = *(const uint4*)((const char*)g_w2t_hi + row * 512 + c * 16);
        *(uint4*)(dyn_smem + G2_BL + off) = *(const uint4*)((const char*)g_w2t_lo + row * 512 + c * 16);
    }

    const int a_r = lid & 15;
    const int a_c = lid >> 4;
    const int b_r = (lid & 7) + ((lid >> 4) << 3);
    const int b_c = (lid >> 3) & 1;
    const int wm = wid * 32;

    float acc[2][5][4];
#pragma unroll
    for (int mt = 0; mt < 2; mt++)
#pragma unroll
        for (int nt = 0; nt < 5; nt++)
#pragma unroll
            for (int r = 0; r < 4; r++) acc[mt][nt][r] = 0.0f;

    for (int kc = 0; kc < 8; kc++) {
        __syncthreads();
        // ---- load A chunk (256 rows x 32 k, hi+lo) ----
#pragma unroll
        for (int i = 0; i < 4; i++) {
            int l = tid + 256 * i;
            int row = l >> 2;
            int c = l & 3;
            unsigned off = row * 80 + c * 16;
            size_t gidx = (size_t)(mBase + row) * HID + kc * 32 + c * 8;
            *(uint4*)(dyn_smem + G2_AH + off) = *(const uint4*)(g_h1hi + gidx);
            *(uint4*)(dyn_smem + G2_AL + off) = *(const uint4*)(g_h1lo + gidx);
        }
        __syncthreads();

#pragma unroll
        for (int ks = 0; ks < 2; ks++) {
            unsigned ah[2][4], al[2][4];
#pragma unroll
            for (int mt = 0; mt < 2; mt++) {
                int row = wm + mt * 16 + a_r;
                unsigned off = row * 80 + (unsigned)(ks * 2 + a_c) * 16;
                ldsm4(ah[mt], sb + G2_AH + off);
                ldsm4(al[mt], sb + G2_AL + off);
            }
            unsigned bh[6][2], bl[6][2];
#pragma unroll
            for (int bt = 0; bt < 3; bt++) {
                int row = bt * 16 + b_r;
                unsigned off = row * 528 + (unsigned)(kc * 4 + ks * 2 + b_c) * 16;
                unsigned t0[4], t1[4];
                ldsm4(t0, sb + G2_BH + off);
                ldsm4(t1, sb + G2_BL + off);
                bh[bt * 2 + 0][0] = t0[0]; bh[bt * 2 + 0][1] = t0[1];
                bh[bt * 2 + 1][0] = t0[2]; bh[bt * 2 + 1][1] = t0[3];
                bl[bt * 2 + 0][0] = t1[0]; bl[bt * 2 + 0][1] = t1[1];
                bl[bt * 2 + 1][0] = t1[2]; bl[bt * 2 + 1][1] = t1[3];
            }
#pragma unroll
            for (int mt = 0; mt < 2; mt++)
#pragma unroll
                for (int nt = 0; nt < 5; nt++) {
                    mma_bf16(acc[mt][nt], ah[mt], bh[nt]);
                    mma_bf16(acc[mt][nt], ah[mt], bl[nt]);
                    mma_bf16(acc[mt][nt], al[mt], bh[nt]);
                }
        }
    }

    // ---- epilogue: store g_y (cols < 40 always; guard rows) ----
    const int rbase = lid >> 2;
    const int cbase = (lid & 3) * 2;
#pragma unroll
    for (int mt = 0; mt < 2; mt++) {
#pragma unroll
        for (int nt = 0; nt < 5; nt++) {
            int n0 = nt * 8 + cbase;
            int m0 = mBase + wm + mt * 16 + rbase;
            if (m0 < NN) {
                float2 v = make_float2(acc[mt][nt][0], acc[mt][nt][1]);
                *(float2*)(g_y + m0 * NCLS + n0) = v;
            }
            if (m0 + 8 < NN) {
                float2 v = make_float2(acc[mt][nt][2], acc[mt][nt][3]);
                *(float2*)(g_y + (m0 + 8) * NCLS + n0) = v;
            }
        }
    }
}

// ---------------- gather2: out[i] = b2 + y[i] + sum y[j] ------------------
__global__ void gather2_kernel(const float* __restrict__ b2, float* __restrict__ out) {
    int h = (blockIdx.x * blockDim.x + threadIdx.x) >> 4;
    int q = threadIdx.x & 15;
    if (h >= NN || q >= 10) return;
    const float4* yb = (const float4*)g_y;
    float4 acc = __ldg((const float4*)b2 + q);
    float4 v = yb[(size_t)h * 10 + q];
    acc.x += v.x; acc.y += v.y; acc.z += v.z; acc.w += v.w;
    int beg = g_rowptr[h];
    int end = g_rowptr[h + 1];
#pragma unroll 2
    for (int e = beg; e < end; e++) {
        int j = g_csr[e];
        float4 u = __ldg(yb + (size_t)j * 10 + q);
        acc.x += u.x; acc.y += u.y; acc.z += u.z; acc.w += u.w;
    }
    ((float4*)out)[(size_t)h * 10 + q] = acc;
}

// --------------------------------------------------------------------------
extern "C" void kernel_launch(void* const* d_in, const int* in_sizes, int n_in,
                              void* d_out, int out_size) {
    const float* x    = (const float*)d_in[0];
    const void*  ei   = d_in[1];
    const float* bn0g = (const float*)d_in[2];
    const float* bn0b = (const float*)d_in[3];
    const float* bn0m = (const float*)d_in[4];
    const float* bn0v = (const float*)d_in[5];
    const float* W1   = (const float*)d_in[6];
    const float* b1   = (const float*)d_in[7];
    const float* bn1g = (const float*)d_in[8];
    const float* bn1b = (const float*)d_in[9];
    const float* bn1m = (const float*)d_in[10];
    const float* bn1v = (const float*)d_in[11];
    const float* W2   = (const float*)d_in[12];
    const float* b2   = (const float*)d_in[13];
    float* out = (float*)d_out;

    cudaFuncSetAttribute(gemm1_kernel, cudaFuncAttributeMaxDynamicSharedMemorySize,
                         G1_SMEM);
    cudaFuncSetAttribute(gemm2_kernel, cudaFuncAttributeMaxDynamicSharedMemorySize,
                         G2_SMEM);

    detect_kernel<<<1, 32>>>((const unsigned int*)ei);
    prep_kernel<<<(FIN * HID + 255) / 256, 256>>>(bn0g, bn0b, bn0m, bn0v, W1, b1,
                                                  bn1g, bn1b, bn1m, bn1v, W2);
    zero_deg_kernel<<<(NN + 255) / 256, 256>>>();
    count_kernel<<<(EE + 255) / 256, 256>>>(ei);
    scan1_kernel<<<NBLK, 1024>>>();
    scan2_kernel<<<1, 32>>>();
    scan3_kernel<<<NBLK, 1024>>>();
    fill_kernel<<<(EE + 255) / 256, 256>>>(ei);
    gather1_kernel<<<(NN * 32 + 255) / 256, 256>>>(x);
    dim3 g1(NNP / 128, HID / 128);
    gemm1_kernel<<<g1, 256, G1_SMEM>>>();
    gemm2_kernel<<<NNP / 256, 256, G2_SMEM>>>();
    gather2_kernel<<<(NN * 16 + 255) / 256, 256>>>(b2, out);
}

// round 7
// speedup vs baseline: 2.7129x; 1.1311x over previous
#include <cuda_runtime.h>
#include <cuda_bf16.h>

#define NN   50000
#define NNP  50176              // padded to multiple of 256
#define FIN  128
#define HID  256
#define NCLS 40
#define EE   600000
#define BN_EPS 1e-5f
#define NBLK ((NN + 1023) / 1024)

// ---------------- device scratch (zero-initialized, no allocs) -----------
__device__ __nv_bfloat16 g_ahi[(size_t)NNP * FIN];   // hi(BN0-folded agg1)
__device__ __nv_bfloat16 g_alo[(size_t)NNP * FIN];   // lo residual
__device__ __nv_bfloat16 g_w1t_hi[HID * FIN];        // W1^T hi  [n][k]
__device__ __nv_bfloat16 g_w1t_lo[HID * FIN];        // W1^T lo
__device__ __nv_bfloat16 g_w2t_hi[48 * HID];         // W2^T hi [n][k], n pad 48
__device__ __nv_bfloat16 g_w2t_lo[48 * HID];         // W2^T lo
__device__ __nv_bfloat16 g_h1hi[(size_t)NNP * HID];  // h1 hi
__device__ __nv_bfloat16 g_h1lo[(size_t)NNP * HID];  // h1 lo
__device__ float g_s0[FIN], g_t0[FIN];               // BN0 affine
__device__ float g_s1[HID], g_d1[HID];               // BN1 scale, b1*s1+t1
__device__ int   g_deg[NN];
__device__ int   g_rowptr[NN + 1];
__device__ int   g_cursor[NN];
__device__ int   g_csr[EE];
__device__ int   g_bsum[NBLK];
__device__ int   g_boff[NBLK];
__device__ float g_y[NN * NCLS];
__device__ int   g_idx64;

// ---------------- mma.sync / ldmatrix helpers (base ISA) ------------------
__device__ __forceinline__ unsigned smem_u32(const void* p) {
    unsigned a;
    asm("{ .reg .u64 t; cvta.to.shared.u64 t, %1; cvt.u32.u64 %0, t; }" : "=r"(a) : "l"(p));
    return a;
}
__device__ __forceinline__ void ldsm4(unsigned* r, unsigned addr) {
    asm volatile("ldmatrix.sync.aligned.m8n8.x4.shared.b16 {%0,%1,%2,%3}, [%4];"
                 : "=r"(r[0]), "=r"(r[1]), "=r"(r[2]), "=r"(r[3]) : "r"(addr));
}
__device__ __forceinline__ void mma_bf16(float* d, const unsigned* a, const unsigned* b) {
    asm volatile(
        "mma.sync.aligned.m16n8k16.row.col.f32.bf16.bf16.f32 "
        "{%0,%1,%2,%3}, {%4,%5,%6,%7}, {%8,%9}, {%0,%1,%2,%3};"
        : "+f"(d[0]), "+f"(d[1]), "+f"(d[2]), "+f"(d[3])
        : "r"(a[0]), "r"(a[1]), "r"(a[2]), "r"(a[3]), "r"(b[0]), "r"(b[1]));
}
__device__ __forceinline__ unsigned packbf2(float a, float b) {
    unsigned r;
    asm("cvt.rn.satfinite.bf16x2.f32 %0, %1, %2;" : "=r"(r) : "f"(b), "f"(a));
    return r;
}

// ---------------- detect (fused with deg zeroing) -------------------------
__global__ void detect_zero_kernel(const unsigned int* __restrict__ ei) {
    int i = blockIdx.x * blockDim.x + threadIdx.x;
    if (i < NN) g_deg[i] = 0;
    if (blockIdx.x == 0 && threadIdx.x < 32) {
        int t = threadIdx.x;
        unsigned any = 0;
        for (int k = t; k < 1024; k += 32) any |= ei[2 * k + 1];
#pragma unroll
        for (int off = 16; off > 0; off >>= 1) any |= __shfl_xor_sync(0xFFFFFFFFu, any, off);
        if (t == 0) g_idx64 = (any == 0) ? 1 : 0;
    }
}

// ---------------- prep: BN affines + W1^T / W2^T bf16 split ---------------
__global__ void prep_kernel(const float* __restrict__ bn0g, const float* __restrict__ bn0b,
                            const float* __restrict__ bn0m, const float* __restrict__ bn0v,
                            const float* __restrict__ W1, const float* __restrict__ b1,
                            const float* __restrict__ bn1g, const float* __restrict__ bn1b,
                            const float* __restrict__ bn1m, const float* __restrict__ bn1v,
                            const float* __restrict__ W2) {
    int t = blockIdx.x * blockDim.x + threadIdx.x;
    if (t < FIN) {
        float s0 = bn0g[t] * rsqrtf(bn0v[t] + BN_EPS);
        g_s0[t] = s0;
        g_t0[t] = bn0b[t] - bn0m[t] * s0;
    }
    if (t < HID) {
        float s1 = bn1g[t] * rsqrtf(bn1v[t] + BN_EPS);
        g_s1[t] = s1;
        g_d1[t] = b1[t] * s1 + (bn1b[t] - bn1m[t] * s1);
    }
    if (t < FIN * HID) {
        int k = t / HID;
        int n = t % HID;
        float w = W1[t];
        __nv_bfloat16 hi = __float2bfloat16_rn(w);
        __nv_bfloat16 lo = __float2bfloat16_rn(w - __bfloat162float(hi));
        g_w1t_hi[n * FIN + k] = hi;
        g_w1t_lo[n * FIN + k] = lo;
    }
    if (t < HID * NCLS) {
        int k = t / NCLS;
        int n = t % NCLS;
        float w = W2[t];
        __nv_bfloat16 hi = __float2bfloat16_rn(w);
        __nv_bfloat16 lo = __float2bfloat16_rn(w - __bfloat162float(hi));
        g_w2t_hi[n * HID + k] = hi;
        g_w2t_lo[n * HID + k] = lo;
    }
}

// ---------------- CSR build ----------------------------------------------
// count: 4 edges per thread (vector dst loads, MLP=4)
__global__ void count_kernel(const void* __restrict__ ei) {
    int t = blockIdx.x * blockDim.x + threadIdx.x;
    if (t >= EE / 4) return;
    int d0, d1, d2, d3;
    if (g_idx64) {
        const longlong2* p = (const longlong2*)((const long long*)ei + EE);
        longlong2 v0 = p[t * 2];
        longlong2 v1 = p[t * 2 + 1];
        d0 = (int)v0.x; d1 = (int)v0.y; d2 = (int)v1.x; d3 = (int)v1.y;
    } else {
        int4 v = ((const int4*)((const int*)ei + EE))[t];
        d0 = v.x; d1 = v.y; d2 = v.z; d3 = v.w;
    }
    atomicAdd(&g_deg[d0], 1);
    atomicAdd(&g_deg[d1], 1);
    atomicAdd(&g_deg[d2], 1);
    atomicAdd(&g_deg[d3], 1);
}
__global__ void scan1_kernel() {
    __shared__ int sh[1024];
    int t = threadIdx.x;
    int i = blockIdx.x * 1024 + t;
    sh[t] = (i < NN) ? g_deg[i] : 0;
    __syncthreads();
#pragma unroll
    for (int off = 512; off > 0; off >>= 1) {
        if (t < off) sh[t] += sh[t + off];
        __syncthreads();
    }
    if (t == 0) g_bsum[blockIdx.x] = sh[0];
}
// single-warp shfl scan over NBLK partials
__global__ void scan2_kernel() {
    int lane = threadIdx.x;
    int carry = 0;
    for (int base = 0; base < NBLK; base += 32) {
        int v = (base + lane < NBLK) ? g_bsum[base + lane] : 0;
        int s = v;
#pragma unroll
        for (int off = 1; off < 32; off <<= 1) {
            int u = __shfl_up_sync(0xFFFFFFFFu, s, off);
            if (lane >= off) s += u;
        }
        if (base + lane < NBLK) g_boff[base + lane] = carry + s - v;
        carry += __shfl_sync(0xFFFFFFFFu, s, 31);
    }
    if (lane == 0) g_rowptr[NN] = carry;
}
__global__ void scan3_kernel() {
    __shared__ int sh[1024];
    int t = threadIdx.x;
    int i = blockIdx.x * 1024 + t;
    int v = (i < NN) ? g_deg[i] : 0;
    sh[t] = v;
    __syncthreads();
#pragma unroll
    for (int off = 1; off < 1024; off <<= 1) {
        int add = (t >= off) ? sh[t - off] : 0;
        __syncthreads();
        sh[t] += add;
        __syncthreads();
    }
    if (i < NN) {
        int excl = sh[t] - v + g_boff[blockIdx.x];
        g_rowptr[i] = excl;
        g_cursor[i] = excl;
    }
}
// fill: 2 edges per thread (vector loads)
__global__ void fill_kernel(const void* __restrict__ ei) {
    int t = blockIdx.x * blockDim.x + threadIdx.x;
    if (t >= EE / 2) return;
    int s0, s1, d0, d1;
    if (g_idx64) {
        longlong2 sv = ((const longlong2*)ei)[t];
        longlong2 dv = ((const longlong2*)((const long long*)ei + EE))[t];
        s0 = (int)sv.x; s1 = (int)sv.y; d0 = (int)dv.x; d1 = (int)dv.y;
    } else {
        int2 sv = ((const int2*)ei)[t];
        int2 dv = ((const int2*)((const int*)ei + EE))[t];
        s0 = sv.x; s1 = sv.y; d0 = dv.x; d1 = dv.y;
    }
    int p0 = atomicAdd(&g_cursor[d0], 1);
    g_csr[p0] = s0;
    int p1 = atomicAdd(&g_cursor[d1], 1);
    g_csr[p1] = s1;
}

// ---------------- gather1: BN0-folded agg, split to bf16 hi/lo ------------
__global__ void gather1_kernel(const float* __restrict__ x) {
    int w = (blockIdx.x * blockDim.x + threadIdx.x) >> 5;   // node
    int q = threadIdx.x & 31;                               // float4 column
    if (w >= NN) return;
    const float4* xb = (const float4*)x;
    float4 acc = __ldg(xb + (size_t)w * 32 + q);
    int beg = g_rowptr[w];
    int end = g_rowptr[w + 1];
#pragma unroll 4
    for (int e = beg; e < end; e++) {
        int j = g_csr[e];
        float4 v = __ldg(xb + (size_t)j * 32 + q);
        acc.x += v.x; acc.y += v.y; acc.z += v.z; acc.w += v.w;
    }
    float cnt = 1.0f + (float)(end - beg);
    float4 s4 = *(const float4*)(g_s0 + 4 * q);
    float4 t4 = *(const float4*)(g_t0 + 4 * q);
    float a0 = acc.x * s4.x + cnt * t4.x;
    float a1 = acc.y * s4.y + cnt * t4.y;
    float a2 = acc.z * s4.z + cnt * t4.z;
    float a3 = acc.w * s4.w + cnt * t4.w;
    __nv_bfloat16 h0 = __float2bfloat16_rn(a0), h1 = __float2bfloat16_rn(a1);
    __nv_bfloat16 h2 = __float2bfloat16_rn(a2), h3 = __float2bfloat16_rn(a3);
    ushort4 hv, lv;
    hv.x = __bfloat16_as_ushort(h0); hv.y = __bfloat16_as_ushort(h1);
    hv.z = __bfloat16_as_ushort(h2); hv.w = __bfloat16_as_ushort(h3);
    lv.x = __bfloat16_as_ushort(__float2bfloat16_rn(a0 - __bfloat162float(h0)));
    lv.y = __bfloat16_as_ushort(__float2bfloat16_rn(a1 - __bfloat162float(h1)));
    lv.z = __bfloat16_as_ushort(__float2bfloat16_rn(a2 - __bfloat162float(h2)));
    lv.w = __bfloat16_as_ushort(__float2bfloat16_rn(a3 - __bfloat162float(h3)));
    size_t base = (size_t)w * FIN + 4 * q;
    *(ushort4*)(g_ahi + base) = hv;
    *(ushort4*)(g_alo + base) = lv;
}

// ---------------- GEMM1: mma.sync bf16x3, 128x256 tile per CTA ------------
// smem: Ah(32K) | Al(32K) | Bh(64K) | Bl(64K) = 192KB, XOR-swizzled rows
#define G1_SMEM 196608
extern __shared__ char dyn_smem[];

__global__ void __launch_bounds__(256, 1) gemm1_kernel() {
    __shared__ float sc1[256], dc1[256];

    const int tid = threadIdx.x;
    const int wid = tid >> 5;
    const int lid = tid & 31;
    const int mBase = blockIdx.x * 128;
    const unsigned sbase = smem_u32(dyn_smem);

    sc1[tid] = g_s1[tid];
    dc1[tid] = g_d1[tid];

    // ---- load A tiles: thread t -> row t/2, chunks (t&1)*8 .. +7 ----
    {
        int row = tid >> 1;
        int half = tid & 1;
        const uint4* ah = (const uint4*)(g_ahi + (size_t)(mBase + row) * FIN);
        const uint4* al = (const uint4*)(g_alo + (size_t)(mBase + row) * FIN);
#pragma unroll
        for (int i = 0; i < 8; i++) {
            int c = half * 8 + i;
            unsigned off = row * 256 + ((unsigned)(c ^ (row & 7))) * 16;
            *(uint4*)(dyn_smem + off) = ah[c];
            *(uint4*)(dyn_smem + 32768 + off) = al[c];
        }
    }
    // ---- load B tiles: thread t -> W1^T row t, all 16 chunks ----
    {
        const uint4* bh = (const uint4*)(g_w1t_hi + (size_t)tid * FIN);
        const uint4* bl = (const uint4*)(g_w1t_lo + (size_t)tid * FIN);
#pragma unroll
        for (int c = 0; c < 16; c++) {
            unsigned off = tid * 256 + ((unsigned)(c ^ (tid & 7))) * 16;
            *(uint4*)(dyn_smem + 65536 + off) = bh[c];
            *(uint4*)(dyn_smem + 131072 + off) = bl[c];
        }
    }
    __syncthreads();

    const int wm = (wid >> 2) * 64;    // warp M offset (0 or 64)
    const int wn = (wid & 3) * 64;     // warp N offset (0,64,128,192)

    float acc[4][8][4];
#pragma unroll
    for (int mt = 0; mt < 4; mt++)
#pragma unroll
        for (int nt = 0; nt < 8; nt++)
#pragma unroll
            for (int r = 0; r < 4; r++) acc[mt][nt][r] = 0.0f;

    const int a_r = lid & 15;
    const int a_c = lid >> 4;
    const int b_r = (lid & 7) + ((lid >> 4) << 3);
    const int b_c = (lid >> 3) & 1;

#pragma unroll
    for (int pass = 0; pass < 3; pass++) {
        unsigned Ab = sbase + ((pass == 2) ? 32768u : 0u);
        unsigned Bb = sbase + 65536u + ((pass == 1) ? 65536u : 0u);
#pragma unroll
        for (int ks = 0; ks < 8; ks++) {
            unsigned a[4][4];
#pragma unroll
            for (int mt = 0; mt < 4; mt++) {
                int row = wm + mt * 16 + a_r;
                int c = ks * 2 + a_c;
                ldsm4(a[mt], Ab + row * 256 + ((unsigned)(c ^ (row & 7))) * 16);
            }
            unsigned b[8][2];
#pragma unroll
            for (int bt = 0; bt < 4; bt++) {
                int row = wn + bt * 16 + b_r;
                int c = ks * 2 + b_c;
                unsigned bb[4];
                ldsm4(bb, Bb + row * 256 + ((unsigned)(c ^ (row & 7))) * 16);
                b[bt * 2 + 0][0] = bb[0]; b[bt * 2 + 0][1] = bb[1];
                b[bt * 2 + 1][0] = bb[2]; b[bt * 2 + 1][1] = bb[3];
            }
#pragma unroll
            for (int mt = 0; mt < 4; mt++)
#pragma unroll
                for (int nt = 0; nt < 8; nt++)
                    mma_bf16(acc[mt][nt], a[mt], b[nt]);
        }
    }

    // ---- epilogue: h = max(d*s1 + (b1*s1+t1), 0), split to bf16 hi/lo ----
    const int rbase = lid >> 2;
    const int cbase = (lid & 3) * 2;
#pragma unroll
    for (int mt = 0; mt < 4; mt++) {
#pragma unroll
        for (int nt = 0; nt < 8; nt++) {
            int n0 = wn + nt * 8 + cbase;
            float s0c = sc1[n0], s1c = sc1[n0 + 1];
            float d0c = dc1[n0], d1c = dc1[n0 + 1];
            int m0 = mBase + wm + mt * 16 + rbase;
#pragma unroll
            for (int half = 0; half < 2; half++) {
                float v0 = fmaxf(acc[mt][nt][half * 2 + 0] * s0c + d0c, 0.0f);
                float v1 = fmaxf(acc[mt][nt][half * 2 + 1] * s1c + d1c, 0.0f);
                unsigned hp = packbf2(v0, v1);
                float h0f = __bfloat162float(__ushort_as_bfloat16((unsigned short)(hp & 0xFFFF)));
                float h1f = __bfloat162float(__ushort_as_bfloat16((unsigned short)(hp >> 16)));
                unsigned lp = packbf2(v0 - h0f, v1 - h1f);
                size_t idx = (size_t)(m0 + half * 8) * HID + n0;
                *(unsigned*)(g_h1hi + idx) = hp;
                *(unsigned*)(g_h1lo + idx) = lp;
            }
        }
    }
}

// ---------------- GEMM2: mma.sync bf16x3, 256x40 tile per CTA -------------
#define G2_SMEM 91648
#define G2_BH 0
#define G2_BL 25344
#define G2_AH 50688
#define G2_AL 71168

__global__ void __launch_bounds__(256, 2) gemm2_kernel() {
    const int tid = threadIdx.x;
    const int wid = tid >> 5;
    const int lid = tid & 31;
    const int mBase = blockIdx.x * 256;
    const unsigned sb = smem_u32(dyn_smem);

    for (int l = tid; l < 48 * 32; l += 256) {
        int row = l >> 5;
        int c = l & 31;
        unsigned off = row * 528 + c * 16;
        *(uint4*)(dyn_smem + G2_BH + off) = *(const uint4*)((const char*)g_w2t_hi + row * 512 + c * 16);
        *(uint4*)(dyn_smem + G2_BL + off) = *(const uint4*)((const char*)g_w2t_lo + row * 512 + c * 16);
    }

    const int a_r = lid & 15;
    const int a_c = lid >> 4;
    const int b_r = (lid & 7) + ((lid >> 4) << 3);
    const int b_c = (lid >> 3) & 1;
    const int wm = wid * 32;

    float acc[2][5][4];
#pragma unroll
    for (int mt = 0; mt < 2; mt++)
#pragma unroll
        for (int nt = 0; nt < 5; nt++)
#pragma unroll
            for (int r = 0; r < 4; r++) acc[mt][nt][r] = 0.0f;

    for (int kc = 0; kc < 8; kc++) {
        __syncthreads();
#pragma unroll
        for (int i = 0; i < 4; i++) {
            int l = tid + 256 * i;
            int row = l >> 2;
            int c = l & 3;
            unsigned off = row * 80 + c * 16;
            size_t gidx = (size_t)(mBase + row) * HID + kc * 32 + c * 8;
            *(uint4*)(dyn_smem + G2_AH + off) = *(const uint4*)(g_h1hi + gidx);
            *(uint4*)(dyn_smem + G2_AL + off) = *(const uint4*)(g_h1lo + gidx);
        }
        __syncthreads();

#pragma unroll
        for (int ks = 0; ks < 2; ks++) {
            unsigned ah[2][4], al[2][4];
#pragma unroll
            for (int mt = 0; mt < 2; mt++) {
                int row = wm + mt * 16 + a_r;
                unsigned off = row * 80 + (unsigned)(ks * 2 + a_c) * 16;
                ldsm4(ah[mt], sb + G2_AH + off);
                ldsm4(al[mt], sb + G2_AL + off);
            }
            unsigned bh[6][2], bl[6][2];
#pragma unroll
            for (int bt = 0; bt < 3; bt++) {
                int row = bt * 16 + b_r;
                unsigned off = row * 528 + (unsigned)(kc * 4 + ks * 2 + b_c) * 16;
                unsigned t0[4], t1[4];
                ldsm4(t0, sb + G2_BH + off);
                ldsm4(t1, sb + G2_BL + off);
                bh[bt * 2 + 0][0] = t0[0]; bh[bt * 2 + 0][1] = t0[1];
                bh[bt * 2 + 1][0] = t0[2]; bh[bt * 2 + 1][1] = t0[3];
                bl[bt * 2 + 0][0] = t1[0]; bl[bt * 2 + 0][1] = t1[1];
                bl[bt * 2 + 1][0] = t1[2]; bl[bt * 2 + 1][1] = t1[3];
            }
#pragma unroll
            for (int mt = 0; mt < 2; mt++)
#pragma unroll
                for (int nt = 0; nt < 5; nt++) {
                    mma_bf16(acc[mt][nt], ah[mt], bh[nt]);
                    mma_bf16(acc[mt][nt], ah[mt], bl[nt]);
                    mma_bf16(acc[mt][nt], al[mt], bh[nt]);
                }
        }
    }

    const int rbase = lid >> 2;
    const int cbase = (lid & 3) * 2;
#pragma unroll
    for (int mt = 0; mt < 2; mt++) {
#pragma unroll
        for (int nt = 0; nt < 5; nt++) {
            int n0 = nt * 8 + cbase;
            int m0 = mBase + wm + mt * 16 + rbase;
            if (m0 < NN) {
                float2 v = make_float2(acc[mt][nt][0], acc[mt][nt][1]);
                *(float2*)(g_y + m0 * NCLS + n0) = v;
            }
            if (m0 + 8 < NN) {
                float2 v = make_float2(acc[mt][nt][2], acc[mt][nt][3]);
                *(float2*)(g_y + (m0 + 8) * NCLS + n0) = v;
            }
        }
    }
}

// ---------------- gather2: out[i] = b2 + y[i] + sum y[j] ------------------
__global__ void gather2_kernel(const float* __restrict__ b2, float* __restrict__ out) {
    int h = (blockIdx.x * blockDim.x + threadIdx.x) >> 4;
    int q = threadIdx.x & 15;
    if (h >= NN || q >= 10) return;
    const float4* yb = (const float4*)g_y;
    float4 acc = __ldg((const float4*)b2 + q);
    float4 v = yb[(size_t)h * 10 + q];
    acc.x += v.x; acc.y += v.y; acc.z += v.z; acc.w += v.w;
    int beg = g_rowptr[h];
    int end = g_rowptr[h + 1];
#pragma unroll 4
    for (int e = beg; e < end; e++) {
        int j = g_csr[e];
        float4 u = __ldg(yb + (size_t)j * 10 + q);
        acc.x += u.x; acc.y += u.y; acc.z += u.z; acc.w += u.w;
    }
    ((float4*)out)[(size_t)h * 10 + q] = acc;
}

// --------------------------------------------------------------------------
extern "C" void kernel_launch(void* const* d_in, const int* in_sizes, int n_in,
                              void* d_out, int out_size) {
    const float* x    = (const float*)d_in[0];
    const void*  ei   = d_in[1];
    const float* bn0g = (const float*)d_in[2];
    const float* bn0b = (const float*)d_in[3];
    const float* bn0m = (const float*)d_in[4];
    const float* bn0v = (const float*)d_in[5];
    const float* W1   = (const float*)d_in[6];
    const float* b1   = (const float*)d_in[7];
    const float* bn1g = (const float*)d_in[8];
    const float* bn1b = (const float*)d_in[9];
    const float* bn1m = (const float*)d_in[10];
    const float* bn1v = (const float*)d_in[11];
    const float* W2   = (const float*)d_in[12];
    const float* b2   = (const float*)d_in[13];
    float* out = (float*)d_out;

    cudaFuncSetAttribute(gemm1_kernel, cudaFuncAttributeMaxDynamicSharedMemorySize,
                         G1_SMEM);
    cudaFuncSetAttribute(gemm2_kernel, cudaFuncAttributeMaxDynamicSharedMemorySize,
                         G2_SMEM);

    detect_zero_kernel<<<(NN + 255) / 256, 256>>>((const unsigned int*)ei);
    prep_kernel<<<(FIN * HID + 255) / 256, 256>>>(bn0g, bn0b, bn0m, bn0v, W1, b1,
                                                  bn1g, bn1b, bn1m, bn1v, W2);
    count_kernel<<<(EE / 4 + 255) / 256, 256>>>(ei);
    scan1_kernel<<<NBLK, 1024>>>();
    scan2_kernel<<<1, 32>>>();
    scan3_kernel<<<NBLK, 1024>>>();
    fill_kernel<<<(EE / 2 + 255) / 256, 256>>>(ei);
    gather1_kernel<<<(NN * 32 + 255) / 256, 256>>>(x);
    gemm1_kernel<<<NNP / 128, 256, G1_SMEM>>>();
    gemm2_kernel<<<NNP / 256, 256, G2_SMEM>>>();
    gather2_kernel<<<(NN * 16 + 255) / 256, 256>>>(b2, out);
}